// round 11
// baseline (speedup 1.0000x reference)
#include <cuda_runtime.h>
#include <cuda_fp16.h>
#include <math.h>
#include <stdint.h>

#define B_ 2
#define L_ 1024
#define HID 2048
#define NH 32
#define HD 64
#define NKV 8
#define INTER 8192
#define DSSM 2048
#define MH 32
#define MP 64
#define MS 64
#define MK 4
#define CONV_DIM (DSSM + 2*MS)          // 2176
#define PROJ_DIM (2*DSSM + 2*MS + MH)   // 4256
#define QKV_DIM (NH*HD + 2*NKV*HD)      // 3072
#define MROWS (B_*L_)                   // 2048

#define ATTN_IN 1.2f
#define ATTN_OUT 0.8f
#define KEY_MULT 0.7f
#define SSM_IN 1.1f
#define SSM_OUT 0.9f
#define GATE_MULT 0.9f
#define DOWN_MULT 0.8f
#define EPS_ 1e-5f

// ---------------- scratch (device globals; no allocation allowed) ----------------
__device__ float  g_proj[MROWS*PROJ_DIM];
__device__ float  g_y   [MROWS*DSSM];
__device__ float  g_as  [MROWS*HID];
__device__ float  g_h   [MROWS*HID];

__device__ __half g_qkv16[MROWS*QKV_DIM];
__device__ __half g_gu16 [(size_t)MROWS*2*INTER];
__device__ __half g_hs16 [MROWS*HID];
__device__ __half g_ctx16[MROWS*HID];
__device__ __half g_gt16 [MROWS*DSSM];
__device__ __half g_hn16 [MROWS*HID];
__device__ __half g_act16[(size_t)MROWS*INTER];
__device__ __half g_q16  [MROWS*NH*HD];
__device__ __half g_k16  [B_*NKV*L_*HD];
__device__ __half g_v16t [B_*NKV*HD*L_];

// fp16 weights, one big buffer
#define W16_QKV     0
#define W16_INPROJ  (W16_QKV    + QKV_DIM*HID)
#define W16_O       (W16_INPROJ + PROJ_DIM*HID)
#define W16_OUTPROJ (W16_O      + HID*HID)
#define W16_GATEUP  (W16_OUTPROJ+ HID*DSSM)
#define W16_DOWN    (W16_GATEUP + 2*INTER*HID)
#define W16_TOTAL   (W16_DOWN   + HID*INTER)
__device__ __half g_w16[W16_TOTAL];

// ---------------- helpers ----------------
__device__ __forceinline__ float blockReduceSum256(float v) {
    __shared__ float sh[8];
    int lane = threadIdx.x & 31, w = threadIdx.x >> 5;
    #pragma unroll
    for (int o = 16; o; o >>= 1) v += __shfl_xor_sync(0xffffffffu, v, o);
    if (lane == 0) sh[w] = v;
    __syncthreads();
    v = (threadIdx.x < 8) ? sh[threadIdx.x] : 0.f;
    if (w == 0) {
        #pragma unroll
        for (int o = 4; o; o >>= 1) v += __shfl_xor_sync(0xffu, v, o);
    }
    return v;
}

__device__ __forceinline__ float siluf(float x) { return x / (1.f + __expf(-x)); }

__device__ __forceinline__ void mma_f16(float* c, const uint32_t* a, const uint32_t* b) {
    asm volatile(
        "mma.sync.aligned.m16n8k16.row.col.f32.f16.f16.f32 "
        "{%0,%1,%2,%3}, {%4,%5,%6,%7}, {%8,%9}, {%0,%1,%2,%3};"
        : "+f"(c[0]), "+f"(c[1]), "+f"(c[2]), "+f"(c[3])
        : "r"(a[0]), "r"(a[1]), "r"(a[2]), "r"(a[3]), "r"(b[0]), "r"(b[1]));
}

__device__ __forceinline__ uint32_t smem_u32(const void* p) {
    uint32_t a;
    asm("{ .reg .u64 t; cvta.to.shared.u64 t, %1; cvt.u32.u64 %0, t; }" : "=r"(a) : "l"(p));
    return a;
}
__device__ __forceinline__ void cp_async16(uint32_t dst, const void* src, int srcBytes) {
    asm volatile("cp.async.cg.shared.global [%0], [%1], 16, %2;"
                 :: "r"(dst), "l"(src), "r"(srcBytes));
}
#define CP_COMMIT() asm volatile("cp.async.commit_group;" ::: "memory")
#define CP_WAIT1()  asm volatile("cp.async.wait_group 1;"  ::: "memory")

__device__ __forceinline__ uint32_t packh2(float a, float b) {
    __half2 h = __floats2half2_rn(a, b);
    return *(uint32_t*)&h;
}

// ---------------- fp32 -> fp16 weight convert (coalesced, 1 float4/thread) -------
__global__ void cvt_f16_kernel(const float* __restrict__ in, __half* __restrict__ out, int n4) {
    int i = blockIdx.x*256 + threadIdx.x;
    if (i >= n4) return;
    float4 v = *(const float4*)(in + (size_t)i*4);
    *(uint2*)(out + (size_t)i*4) = make_uint2(packh2(v.x, v.y), packh2(v.z, v.w));
}

// ---------------- FP16 tensor-core GEMM (fp32 out, alpha/beta) ----------------
#define TBM 128
#define TBN 128
#define TBK 64
#define TSTP 36
#define STGP (128*TSTP)
#define GSMEM_BYTES (4*STGP*4)           // 73728 B

__global__ __launch_bounds__(256, 2) void gemm_f16(
    int Ni, int Ki, float alpha,
    const __half* __restrict__ A, const __half* __restrict__ Bw,
    float beta, const float* __restrict__ Cin, float* __restrict__ C)
{
    extern __shared__ uint32_t smp[];
    uint32_t* As[2] = { smp,          smp + 2*STGP };
    uint32_t* Bs[2] = { smp + STGP,   smp + 3*STGP };

    const int tid = threadIdx.x;
    const int bm = blockIdx.y * TBM, bn = blockIdx.x * TBN;
    const int warp = tid >> 5, lane = tid & 31;
    const int g = lane >> 2, t = lane & 3;
    const int wm = (warp >> 2) * 64;
    const int wn = (warp & 3) * 32;

    const int lrow = tid >> 3;
    const int lch  = tid & 7;

    const int nk = Ki / TBK;

    {
        #pragma unroll
        for (int q = 0; q < 4; ++q) {
            int row = lrow + q*32;
            cp_async16(smem_u32(As[0] + row*TSTP + lch*4),
                       A + (size_t)(bm + row)*Ki + lch*8, 16);
            int brow = bn + row;
            const __half* srcB = Bw + (size_t)(brow < Ni ? brow : 0)*Ki + lch*8;
            cp_async16(smem_u32(Bs[0] + row*TSTP + lch*4), srcB, brow < Ni ? 16 : 0);
        }
        CP_COMMIT();
    }

    float acc[4][4][4];
    #pragma unroll
    for (int i = 0; i < 4; ++i)
        #pragma unroll
        for (int j = 0; j < 4; ++j)
            #pragma unroll
            for (int r = 0; r < 4; ++r) acc[i][j][r] = 0.f;

    for (int j = 0; j < nk; ++j) {
        const int b = j & 1;
        if (j + 1 < nk) {
            const int k0 = (j + 1) * TBK;
            const int nb = b ^ 1;
            #pragma unroll
            for (int q = 0; q < 4; ++q) {
                int row = lrow + q*32;
                cp_async16(smem_u32(As[nb] + row*TSTP + lch*4),
                           A + (size_t)(bm + row)*Ki + k0 + lch*8, 16);
                int brow = bn + row;
                const __half* srcB = Bw + (size_t)(brow < Ni ? brow : 0)*Ki + k0 + lch*8;
                cp_async16(smem_u32(Bs[nb] + row*TSTP + lch*4), srcB, brow < Ni ? 16 : 0);
            }
        }
        CP_COMMIT();
        CP_WAIT1();
        __syncthreads();

        const uint32_t* as = As[b];
        const uint32_t* bs = Bs[b];
        #pragma unroll
        for (int ks = 0; ks < TBK/16; ++ks) {
            uint32_t af[4][4];
            #pragma unroll
            for (int i = 0; i < 4; ++i) {
                const uint32_t* r0 = as + (wm + i*16 + g)*TSTP + ks*8 + t;
                const uint32_t* r1 = r0 + 8*TSTP;
                af[i][0] = r0[0];
                af[i][1] = r1[0];
                af[i][2] = r0[4];
                af[i][3] = r1[4];
            }
            uint32_t bf[4][2];
            #pragma unroll
            for (int jj = 0; jj < 4; ++jj) {
                const uint32_t* base = bs + (wn + jj*8 + g)*TSTP + ks*8 + t;
                bf[jj][0] = base[0];
                bf[jj][1] = base[4];
            }
            #pragma unroll
            for (int i = 0; i < 4; ++i)
                #pragma unroll
                for (int jj = 0; jj < 4; ++jj)
                    mma_f16(acc[i][jj], af[i], bf[jj]);
        }
        __syncthreads();
    }

    #pragma unroll
    for (int i = 0; i < 4; ++i) {
        int row0 = bm + wm + i*16 + g;
        #pragma unroll
        for (int j = 0; j < 4; ++j) {
            int col = bn + wn + j*8 + 2*t;
            if (col >= Ni) continue;
            size_t o0 = (size_t)row0 * Ni + col;
            size_t o1 = (size_t)(row0 + 8) * Ni + col;
            float2 v0 = make_float2(alpha*acc[i][j][0], alpha*acc[i][j][1]);
            float2 v1 = make_float2(alpha*acc[i][j][2], alpha*acc[i][j][3]);
            if (beta != 0.f) {
                float2 e0 = *(const float2*)(Cin + o0);
                float2 e1 = *(const float2*)(Cin + o1);
                v0.x += beta*e0.x; v0.y += beta*e0.y;
                v1.x += beta*e1.x; v1.y += beta*e1.y;
            }
            *(float2*)(C + o0) = v0;
            *(float2*)(C + o1) = v1;
        }
    }
}

// ---------------- FP16 GEMM, fp16 output (alpha only) ----------------
__global__ __launch_bounds__(256, 2) void gemm_f16h(
    int Ni, int Ki, float alpha,
    const __half* __restrict__ A, const __half* __restrict__ Bw,
    __half* __restrict__ C)
{
    extern __shared__ uint32_t smp[];
    uint32_t* As[2] = { smp,          smp + 2*STGP };
    uint32_t* Bs[2] = { smp + STGP,   smp + 3*STGP };

    const int tid = threadIdx.x;
    const int bm = blockIdx.y * TBM, bn = blockIdx.x * TBN;
    const int warp = tid >> 5, lane = tid & 31;
    const int g = lane >> 2, t = lane & 3;
    const int wm = (warp >> 2) * 64;
    const int wn = (warp & 3) * 32;

    const int lrow = tid >> 3;
    const int lch  = tid & 7;

    const int nk = Ki / TBK;

    {
        #pragma unroll
        for (int q = 0; q < 4; ++q) {
            int row = lrow + q*32;
            cp_async16(smem_u32(As[0] + row*TSTP + lch*4),
                       A + (size_t)(bm + row)*Ki + lch*8, 16);
            int brow = bn + row;
            const __half* srcB = Bw + (size_t)(brow < Ni ? brow : 0)*Ki + lch*8;
            cp_async16(smem_u32(Bs[0] + row*TSTP + lch*4), srcB, brow < Ni ? 16 : 0);
        }
        CP_COMMIT();
    }

    float acc[4][4][4];
    #pragma unroll
    for (int i = 0; i < 4; ++i)
        #pragma unroll
        for (int j = 0; j < 4; ++j)
            #pragma unroll
            for (int r = 0; r < 4; ++r) acc[i][j][r] = 0.f;

    for (int j = 0; j < nk; ++j) {
        const int b = j & 1;
        if (j + 1 < nk) {
            const int k0 = (j + 1) * TBK;
            const int nb = b ^ 1;
            #pragma unroll
            for (int q = 0; q < 4; ++q) {
                int row = lrow + q*32;
                cp_async16(smem_u32(As[nb] + row*TSTP + lch*4),
                           A + (size_t)(bm + row)*Ki + k0 + lch*8, 16);
                int brow = bn + row;
                const __half* srcB = Bw + (size_t)(brow < Ni ? brow : 0)*Ki + k0 + lch*8;
                cp_async16(smem_u32(Bs[nb] + row*TSTP + lch*4), srcB, brow < Ni ? 16 : 0);
            }
        }
        CP_COMMIT();
        CP_WAIT1();
        __syncthreads();

        const uint32_t* as = As[b];
        const uint32_t* bs = Bs[b];
        #pragma unroll
        for (int ks = 0; ks < TBK/16; ++ks) {
            uint32_t af[4][4];
            #pragma unroll
            for (int i = 0; i < 4; ++i) {
                const uint32_t* r0 = as + (wm + i*16 + g)*TSTP + ks*8 + t;
                const uint32_t* r1 = r0 + 8*TSTP;
                af[i][0] = r0[0];
                af[i][1] = r1[0];
                af[i][2] = r0[4];
                af[i][3] = r1[4];
            }
            uint32_t bf[4][2];
            #pragma unroll
            for (int jj = 0; jj < 4; ++jj) {
                const uint32_t* base = bs + (wn + jj*8 + g)*TSTP + ks*8 + t;
                bf[jj][0] = base[0];
                bf[jj][1] = base[4];
            }
            #pragma unroll
            for (int i = 0; i < 4; ++i)
                #pragma unroll
                for (int jj = 0; jj < 4; ++jj)
                    mma_f16(acc[i][jj], af[i], bf[jj]);
        }
        __syncthreads();
    }

    #pragma unroll
    for (int i = 0; i < 4; ++i) {
        int row0 = bm + wm + i*16 + g;
        #pragma unroll
        for (int j = 0; j < 4; ++j) {
            int col = bn + wn + j*8 + 2*t;
            if (col >= Ni) continue;
            *(uint32_t*)(C + (size_t)row0 * Ni + col) =
                packh2(alpha*acc[i][j][0], alpha*acc[i][j][1]);
            *(uint32_t*)(C + (size_t)(row0 + 8) * Ni + col) =
                packh2(alpha*acc[i][j][2], alpha*acc[i][j][3]);
        }
    }
}

// ---------------- RMS norm: hs16 = f16(rms(x)*w) ----------------
__global__ __launch_bounds__(256) void rms_kernel(
    const float* __restrict__ x, const float* __restrict__ w, __half* __restrict__ out)
{
    int m = blockIdx.x;
    const float* xr = x + (size_t)m * HID;
    float v[8]; float ss = 0.f;
    #pragma unroll
    for (int k = 0; k < 8; ++k) { v[k] = xr[threadIdx.x + k*256]; ss += v[k]*v[k]; }
    ss = blockReduceSum256(ss);
    __shared__ float s_inv;
    if (threadIdx.x == 0) s_inv = rsqrtf(ss * (1.f/HID) + EPS_);
    __syncthreads();
    float inv = s_inv;
    __half* o = out + (size_t)m * HID;
    #pragma unroll
    for (int k = 0; k < 8; ++k) { int c = threadIdx.x + k*256; o[c] = __float2half_rn(v[k]*inv*w[c]); }
}

// ---------------- RoPE on fp16 qkv -> fp16 q (x1/8) and k (head-major) ----------
__global__ void rope_kernel(const __half* __restrict__ qkv, const int* __restrict__ positions,
                            __half* __restrict__ q16, __half* __restrict__ k16) {
    int idx = blockIdx.x*256 + threadIdx.x;
    const int total = MROWS*(NH+NKV)*32;
    if (idx >= total) return;
    int i = idx & 31; int rest = idx >> 5;
    int head = rest % (NH+NKV); int ml = rest / (NH+NKV);
    int l = ml % L_, b = ml / L_;
    float inv = powf(1e11f, -(float)i/32.0f);
    float ang = (float)positions[l] * inv;
    float c = cosf(ang), s = sinf(ang);
    if (head < NH) {
        const __half* p = qkv + (size_t)ml*QKV_DIM + head*HD;
        float x1 = __half2float(p[i]), x2 = __half2float(p[i+32]);
        __half* o = q16 + (size_t)ml*(NH*HD) + head*HD;
        o[i]    = __float2half_rn((x1*c - x2*s) * 0.125f);
        o[i+32] = __float2half_rn((x2*c + x1*s) * 0.125f);
    } else {
        int g = head - NH;
        const __half* p = qkv + (size_t)ml*QKV_DIM + NH*HD + g*HD;
        float x1 = __half2float(p[i])*KEY_MULT, x2 = __half2float(p[i+32])*KEY_MULT;
        __half* o = k16 + ((size_t)(b*NKV + g)*L_ + l)*HD;
        o[i]    = __float2half_rn(x1*c - x2*s);
        o[i+32] = __float2half_rn(x2*c + x1*s);
    }
}

// ---------------- V transpose: fp16 qkv v-part -> v16t [b][g][d][L] --------------
__global__ __launch_bounds__(256) void vtrans_kernel(
    const __half* __restrict__ qkv, __half* __restrict__ v16t)
{
    __shared__ __half ts[64][65];
    const int lt = blockIdx.x, g = blockIdx.y, b = blockIdx.z;
    const int vcol = NH*HD + NKV*HD + g*HD;
    const int tid = threadIdx.x;
    #pragma unroll
    for (int q = 0; q < 16; ++q) {
        int idx = tid + q*256;
        int row = idx >> 6, col = idx & 63;
        ts[col][row] = qkv[(size_t)(b*L_ + lt*64 + row)*QKV_DIM + vcol + col];
    }
    __syncthreads();
    #pragma unroll
    for (int q = 0; q < 16; ++q) {
        int idx = tid + q*256;
        int d = idx >> 6, l = idx & 63;
        v16t[((size_t)(b*NKV + g)*HD + d)*L_ + lt*64 + l] = ts[d][l];
    }
}

// ---------------- tensor-core flash attention (causal, GQA, HD=64) --------------
__global__ __launch_bounds__(128) void attn_kernel(
    const __half* __restrict__ q16, const __half* __restrict__ k16,
    const __half* __restrict__ v16t, __half* __restrict__ ctx)
{
    __shared__ uint32_t Qs[64*36];
    __shared__ uint32_t Ks[64*36];
    __shared__ uint32_t Vs[64*36];
    const int tid = threadIdx.x;
    const int warp = tid >> 5, lane = tid & 31;
    const int g = lane >> 2, t = lane & 3;
    const int wm = warp*16;
    const int qb = blockIdx.x, h = blockIdx.y, b = blockIdx.z;
    const int kg = h >> 2;

    {
        const __half* qp = q16 + (size_t)(b*L_ + qb*64)*(NH*HD) + h*HD;
        #pragma unroll
        for (int q = 0; q < 4; ++q) {
            int idx = tid + q*128;
            int row = idx >> 3, ch = idx & 7;
            *(uint4*)(&Qs[row*36 + ch*4]) =
                *(const uint4*)(qp + (size_t)row*(NH*HD) + ch*8);
        }
    }
    __syncthreads();

    uint32_t aq[4][4];
    #pragma unroll
    for (int ks = 0; ks < 4; ++ks) {
        const uint32_t* r0 = Qs + (wm + g)*36 + ks*8 + t;
        const uint32_t* r1 = Qs + (wm + g + 8)*36 + ks*8 + t;
        aq[ks][0] = r0[0]; aq[ks][1] = r1[0]; aq[ks][2] = r0[4]; aq[ks][3] = r1[4];
    }

    float oacc[8][4];
    #pragma unroll
    for (int jj = 0; jj < 8; ++jj)
        #pragma unroll
        for (int r = 0; r < 4; ++r) oacc[jj][r] = 0.f;
    float m_a = -1e30f, m_b = -1e30f, l_a = 0.f, l_b = 0.f;

    const __half* kp = k16 + (size_t)(b*NKV + kg)*L_*HD;
    const __half* vp = v16t + (size_t)(b*NKV + kg)*HD*L_;

    for (int j = 0; j <= qb; ++j) {
        __syncthreads();
        #pragma unroll
        for (int q = 0; q < 4; ++q) {
            int idx = tid + q*128;
            int row = idx >> 3, ch = idx & 7;
            *(uint4*)(&Ks[row*36 + ch*4]) =
                *(const uint4*)(kp + (size_t)(j*64 + row)*HD + ch*8);
            *(uint4*)(&Vs[row*36 + ch*4]) =
                *(const uint4*)(vp + (size_t)row*L_ + j*64 + ch*8);
        }
        __syncthreads();

        float sacc[8][4];
        #pragma unroll
        for (int jj = 0; jj < 8; ++jj)
            #pragma unroll
            for (int r = 0; r < 4; ++r) sacc[jj][r] = 0.f;
        #pragma unroll
        for (int ks = 0; ks < 4; ++ks) {
            #pragma unroll
            for (int jj = 0; jj < 8; ++jj) {
                uint32_t bk[2];
                const uint32_t* base = Ks + (jj*8 + g)*36 + ks*8 + t;
                bk[0] = base[0]; bk[1] = base[4];
                mma_f16(sacc[jj], aq[ks], bk);
            }
        }

        if (j == qb) {
            const int ra = wm + g, rb = ra + 8;
            #pragma unroll
            for (int jj = 0; jj < 8; ++jj) {
                int c0 = jj*8 + 2*t, c1 = c0 + 1;
                if (c0 > ra) sacc[jj][0] = -1e30f;
                if (c1 > ra) sacc[jj][1] = -1e30f;
                if (c0 > rb) sacc[jj][2] = -1e30f;
                if (c1 > rb) sacc[jj][3] = -1e30f;
            }
        }

        float mx_a = -1e30f, mx_b = -1e30f;
        #pragma unroll
        for (int jj = 0; jj < 8; ++jj) {
            mx_a = fmaxf(mx_a, fmaxf(sacc[jj][0], sacc[jj][1]));
            mx_b = fmaxf(mx_b, fmaxf(sacc[jj][2], sacc[jj][3]));
        }
        mx_a = fmaxf(mx_a, __shfl_xor_sync(0xffffffffu, mx_a, 1));
        mx_a = fmaxf(mx_a, __shfl_xor_sync(0xffffffffu, mx_a, 2));
        mx_b = fmaxf(mx_b, __shfl_xor_sync(0xffffffffu, mx_b, 1));
        mx_b = fmaxf(mx_b, __shfl_xor_sync(0xffffffffu, mx_b, 2));
        float mna = fmaxf(m_a, mx_a), mnb = fmaxf(m_b, mx_b);
        float ca = __expf(m_a - mna), cb = __expf(m_b - mnb);
        m_a = mna; m_b = mnb;
        float sa = 0.f, sb = 0.f;
        #pragma unroll
        for (int jj = 0; jj < 8; ++jj) {
            sacc[jj][0] = __expf(sacc[jj][0] - mna);
            sacc[jj][1] = __expf(sacc[jj][1] - mna);
            sacc[jj][2] = __expf(sacc[jj][2] - mnb);
            sacc[jj][3] = __expf(sacc[jj][3] - mnb);
            sa += sacc[jj][0] + sacc[jj][1];
            sb += sacc[jj][2] + sacc[jj][3];
        }
        sa += __shfl_xor_sync(0xffffffffu, sa, 1);
        sa += __shfl_xor_sync(0xffffffffu, sa, 2);
        sb += __shfl_xor_sync(0xffffffffu, sb, 1);
        sb += __shfl_xor_sync(0xffffffffu, sb, 2);
        l_a = l_a*ca + sa; l_b = l_b*cb + sb;
        #pragma unroll
        for (int jj = 0; jj < 8; ++jj) {
            oacc[jj][0] *= ca; oacc[jj][1] *= ca;
            oacc[jj][2] *= cb; oacc[jj][3] *= cb;
        }

        uint32_t aP[4][4];
        #pragma unroll
        for (int s = 0; s < 4; ++s) {
            aP[s][0] = packh2(sacc[2*s][0],   sacc[2*s][1]);
            aP[s][1] = packh2(sacc[2*s][2],   sacc[2*s][3]);
            aP[s][2] = packh2(sacc[2*s+1][0], sacc[2*s+1][1]);
            aP[s][3] = packh2(sacc[2*s+1][2], sacc[2*s+1][3]);
        }

        #pragma unroll
        for (int s = 0; s < 4; ++s) {
            #pragma unroll
            for (int jj = 0; jj < 8; ++jj) {
                uint32_t bv[2];
                const uint32_t* base = Vs + (jj*8 + g)*36 + s*8 + t;
                bv[0] = base[0]; bv[1] = base[4];
                mma_f16(oacc[jj], aP[s], bv);
            }
        }
    }

    float ila = 1.f / l_a, ilb = 1.f / l_b;
    int ra = qb*64 + wm + g;
    __half* op = ctx + (size_t)(b*L_ + ra)*HID + h*HD + 2*t;
    #pragma unroll
    for (int jj = 0; jj < 8; ++jj) {
        *(uint32_t*)(op + jj*8) = packh2(oacc[jj][0]*ila, oacc[jj][1]*ila);
        *(uint32_t*)(op + 8*HID + jj*8) = packh2(oacc[jj][2]*ilb, oacc[jj][3]*ilb);
    }
}

// ---------------- Mamba2 selective scan with fused depthwise conv ----------------
#define SCT 32
__global__ __launch_bounds__(256) void scan_kernel(
    const float* __restrict__ proj, const float* __restrict__ cw,
    const float* __restrict__ cb,
    const float* __restrict__ A_log, const float* __restrict__ dt_bias,
    const float* __restrict__ Dp, float* __restrict__ y)
{
    const int b = blockIdx.x / MH, h = blockIdx.x % MH;
    const int tid = threadIdx.x;
    const int p = tid >> 2, sg = tid & 3, s0 = sg*16;
    const float Ah = -__expf(A_log[h]);
    const float Dh = Dp[h];
    const float dtb = dt_bias[h];
    float st[16];
    #pragma unroll
    for (int i = 0; i < 16; ++i) st[i] = 0.f;

    __shared__ float xs[SCT][64], Bsh[SCT][64], Csh[SCT][64], dts[SCT];
    __shared__ float wx[64][4], wB[64][4], wC[64][4];
    __shared__ float bx[64], bB[64], bC[64];

    if (tid < 64) {
        int c = tid;
        #pragma unroll
        for (int k = 0; k < MK; ++k) {
            wx[c][k] = cw[(h*64 + c)*MK + k];
            wB[c][k] = cw[(DSSM + c)*MK + k];
            wC[c][k] = cw[(DSSM + MS + c)*MK + k];
        }
        bx[c] = cb[h*64 + c];
        bB[c] = cb[DSSM + c];
        bC[c] = cb[DSSM + MS + c];
    }
    __syncthreads();

    for (int l0 = 0; l0 < L_; l0 += SCT) {
        __syncthreads();
        for (int i = tid; i < SCT*64; i += 256) {
            int t = i >> 6, c = i & 63;
            int l = l0 + t;
            float sx = 0.f, sB = 0.f, sC = 0.f;
            #pragma unroll
            for (int k = 0; k < MK; ++k) {
                int ls = l + k - (MK-1);
                if (ls >= 0) {
                    const float* pr = proj + (size_t)(b*L_ + ls)*PROJ_DIM + DSSM;
                    sx += pr[h*64 + c]      * wx[c][k];
                    sB += pr[DSSM + c]      * wB[c][k];
                    sC += pr[DSSM + MS + c] * wC[c][k];
                }
            }
            xs[t][c]  = siluf(0.9f*sx + bx[c]);
            Bsh[t][c] = siluf(0.8f*sB + bB[c]);
            Csh[t][c] = siluf(1.1f*sC + bC[c]);
        }
        for (int i = tid; i < SCT; i += 256) {
            float r = proj[(size_t)(b*L_ + l0 + i)*PROJ_DIM + (PROJ_DIM-MH) + h] * 1.2f + dtb;
            dts[i] = (r > 20.f) ? r : log1pf(expf(r));   // softplus
        }
        __syncthreads();
        for (int t = 0; t < SCT; ++t) {
            float dt = dts[t];
            float dA = __expf(dt * Ah);
            float xv = xs[t][p];
            float coef = dt * xv;
            float acc = 0.f;
            #pragma unroll
            for (int ss = 0; ss < 16; ++ss) {
                st[ss] = st[ss]*dA + coef*Bsh[t][s0+ss];
                acc = fmaf(st[ss], Csh[t][s0+ss], acc);
            }
            acc += __shfl_xor_sync(0xffffffffu, acc, 1);
            acc += __shfl_xor_sync(0xffffffffu, acc, 2);
            if (sg == 0)
                y[(size_t)(b*L_ + l0 + t)*DSSM + h*64 + p] = acc + xv*Dh;
        }
    }
}

// ---------------- gating + RMS -> fp16 ----------------
__global__ __launch_bounds__(256) void gate_rms_kernel(
    const float* __restrict__ y, const float* __restrict__ proj,
    const float* __restrict__ w, __half* __restrict__ out)
{
    int m = blockIdx.x;
    const float* yr = y + (size_t)m*DSSM;
    const float* zr = proj + (size_t)m*PROJ_DIM;
    float v[8]; float ss = 0.f;
    #pragma unroll
    for (int k = 0; k < 8; ++k) {
        int c = threadIdx.x + k*256;
        float z = zr[c];
        float gv = yr[c] * siluf(z);
        v[k] = gv; ss += gv*gv;
    }
    ss = blockReduceSum256(ss);
    __shared__ float s_inv;
    if (threadIdx.x == 0) s_inv = rsqrtf(ss * (1.f/DSSM) + EPS_);
    __syncthreads();
    float inv = s_inv;
    __half* o = out + (size_t)m*DSSM;
    #pragma unroll
    for (int k = 0; k < 8; ++k) { int c = threadIdx.x + k*256; o[c] = __float2half_rn(v[k]*inv*w[c]); }
}

// ---------------- combine: h = as + residual ; hn16 = f16(rms(h)*w) ----------------
__global__ __launch_bounds__(256) void combine_kernel(
    const float* __restrict__ as_, const float* __restrict__ resid,
    const float* __restrict__ w, float* __restrict__ h, __half* __restrict__ hn)
{
    int m = blockIdx.x;
    const float* ar = as_  + (size_t)m*HID;
    const float* rr = resid + (size_t)m*HID;
    float v[8]; float ss = 0.f;
    #pragma unroll
    for (int k = 0; k < 8; ++k) {
        int c = threadIdx.x + k*256;
        float hv = ar[c] + rr[c];
        v[k] = hv; ss += hv*hv;
    }
    ss = blockReduceSum256(ss);
    __shared__ float s_inv;
    if (threadIdx.x == 0) s_inv = rsqrtf(ss * (1.f/HID) + EPS_);
    __syncthreads();
    float inv = s_inv;
    float* ho = h + (size_t)m*HID;
    __half* no = hn + (size_t)m*HID;
    #pragma unroll
    for (int k = 0; k < 8; ++k) {
        int c = threadIdx.x + k*256;
        ho[c] = v[k];
        no[c] = __float2half_rn(v[k]*inv*w[c]);
    }
}

// ---------------- SwiGLU activation on fp16 gu -> fp16 ----------------
__global__ void act_kernel(const __half* __restrict__ gu, __half* __restrict__ act) {
    int idx = blockIdx.x*256 + threadIdx.x;
    if (idx >= MROWS*INTER/2) return;
    int m = idx / (INTER/2);
    int i = (idx % (INTER/2)) * 2;
    const __half* row = gu + (size_t)m*(2*INTER);
    __half2 g2 = *(const __half2*)(row + i);
    __half2 u2 = *(const __half2*)(row + INTER + i);
    float g0 = __half2float(g2.x) * GATE_MULT;
    float g1 = __half2float(g2.y) * GATE_MULT;
    float a0 = siluf(g0) * __half2float(u2.x);
    float a1 = siluf(g1) * __half2float(u2.y);
    *(uint32_t*)(act + (size_t)m*INTER + i) = packh2(a0, a1);
}

// ---------------- host launcher ----------------
extern "C" void kernel_launch(void* const* d_in, const int* in_sizes, int n_in,
                              void* d_out, int out_size)
{
    const float* hidden      = (const float*)d_in[0];
    const int*   positions   = (const int*)  d_in[1];
    const float* w_in_ln     = (const float*)d_in[2];
    const float* qkv_w       = (const float*)d_in[3];
    const float* o_w         = (const float*)d_in[4];
    const float* in_proj_w   = (const float*)d_in[5];
    const float* conv_w      = (const float*)d_in[6];
    const float* conv_b      = (const float*)d_in[7];
    const float* A_log       = (const float*)d_in[8];
    const float* dt_bias     = (const float*)d_in[9];
    const float* Dp          = (const float*)d_in[10];
    const float* ssm_norm_w  = (const float*)d_in[11];
    const float* out_proj_w  = (const float*)d_in[12];
    const float* w_pre_ff_ln = (const float*)d_in[13];
    const float* gate_up_w   = (const float*)d_in[14];
    const float* down_w      = (const float*)d_in[15];
    float* out = (float*)d_out;

    float *proj, *y, *as_, *h;
    __half *qkv16, *gu16, *hs16, *ctx16, *gt16, *hn16, *act16, *w16, *q16, *k16, *v16t;
    cudaGetSymbolAddress((void**)&proj, g_proj);
    cudaGetSymbolAddress((void**)&y,    g_y);
    cudaGetSymbolAddress((void**)&as_,  g_as);
    cudaGetSymbolAddress((void**)&h,    g_h);
    cudaGetSymbolAddress((void**)&qkv16,g_qkv16);
    cudaGetSymbolAddress((void**)&gu16, g_gu16);
    cudaGetSymbolAddress((void**)&hs16, g_hs16);
    cudaGetSymbolAddress((void**)&ctx16,g_ctx16);
    cudaGetSymbolAddress((void**)&gt16, g_gt16);
    cudaGetSymbolAddress((void**)&hn16, g_hn16);
    cudaGetSymbolAddress((void**)&act16,g_act16);
    cudaGetSymbolAddress((void**)&w16,  g_w16);
    cudaGetSymbolAddress((void**)&q16,  g_q16);
    cudaGetSymbolAddress((void**)&k16,  g_k16);
    cudaGetSymbolAddress((void**)&v16t, g_v16t);

    cudaFuncSetAttribute(gemm_f16,  cudaFuncAttributeMaxDynamicSharedMemorySize, GSMEM_BYTES);
    cudaFuncSetAttribute(gemm_f16h, cudaFuncAttributeMaxDynamicSharedMemorySize, GSMEM_BYTES);

    const int MT = MROWS/TBM;   // 16

    // 0. weight conversion fp32 -> fp16 (coalesced)
    #define CVT(src, dstoff, n) \
        cvt_f16_kernel<<<((n)/4 + 255)/256, 256>>>(src, w16 + (size_t)(dstoff), (n)/4)
    CVT(qkv_w,      W16_QKV,     QKV_DIM*HID);
    CVT(in_proj_w,  W16_INPROJ,  PROJ_DIM*HID);
    CVT(o_w,        W16_O,       HID*HID);
    CVT(out_proj_w, W16_OUTPROJ, HID*DSSM);
    CVT(gate_up_w,  W16_GATEUP,  2*INTER*HID);
    CVT(down_w,     W16_DOWN,    HID*INTER);
    #undef CVT

    // 1. input RMS norm (fp16 out)
    rms_kernel<<<MROWS, 256>>>(hidden, w_in_ln, hs16);

    // 2. qkv (fp16 out) ; proj (fp32)
    gemm_f16h<<<dim3(QKV_DIM/TBN, MT), 256, GSMEM_BYTES>>>(QKV_DIM, HID, ATTN_IN,
                                            hs16, w16 + W16_QKV, qkv16);
    gemm_f16<<<dim3((PROJ_DIM+TBN-1)/TBN, MT), 256, GSMEM_BYTES>>>(PROJ_DIM, HID, SSM_IN,
                                            hs16, w16 + W16_INPROJ, 0.f, nullptr, proj);

    // 3. RoPE -> fp16 q/k ; V transpose -> fp16
    rope_kernel<<<(MROWS*(NH+NKV)*32 + 255)/256, 256>>>(qkv16, positions, q16, k16);
    vtrans_kernel<<<dim3(L_/64, NKV, B_), 256>>>(qkv16, v16t);

    // 4. tensor-core flash attention (fp16 ctx out)
    attn_kernel<<<dim3(L_/64, NH, B_), 128>>>(q16, k16, v16t, ctx16);

    // 5. as = ATTN_OUT * ctx @ o_w^T
    gemm_f16<<<dim3(HID/TBN, MT), 256, GSMEM_BYTES>>>(HID, HID, ATTN_OUT,
                                            ctx16, w16 + W16_O, 0.f, nullptr, as_);

    // 6. mamba: fused conv+scan -> gate+rms -> out_proj (accumulate into as)
    scan_kernel<<<B_*MH, 256>>>(proj, conv_w, conv_b, A_log, dt_bias, Dp, y);
    gate_rms_kernel<<<MROWS, 256>>>(y, proj, ssm_norm_w, gt16);
    gemm_f16<<<dim3(HID/TBN, MT), 256, GSMEM_BYTES>>>(HID, DSSM, SSM_OUT,
                                            gt16, w16 + W16_OUTPROJ, 1.f, as_, as_);

    // 7. combine + pre-FF RMS (fp16 hn out)
    combine_kernel<<<MROWS, 256>>>(as_, hidden, w_pre_ff_ln, h, hn16);

    // 8. MLP: gate_up (fp16 gu) -> act -> down
    gemm_f16h<<<dim3(2*INTER/TBN, MT), 256, GSMEM_BYTES>>>(2*INTER, HID, 1.f,
                                            hn16, w16 + W16_GATEUP, gu16);
    act_kernel<<<(MROWS*INTER/2 + 255)/256, 256>>>(gu16, act16);
    gemm_f16<<<dim3(HID/TBN, MT), 256, GSMEM_BYTES>>>(HID, INTER, DOWN_MULT,
                                            act16, w16 + W16_DOWN, 1.f, h, out);
    (void)in_sizes; (void)n_in; (void)out_size;
}

// round 13
// speedup vs baseline: 1.2174x; 1.2174x over previous
#include <cuda_runtime.h>
#include <cuda_fp16.h>
#include <math.h>
#include <stdint.h>

#define B_ 2
#define L_ 1024
#define HID 2048
#define NH 32
#define HD 64
#define NKV 8
#define INTER 8192
#define DSSM 2048
#define MH 32
#define MP 64
#define MS 64
#define MK 4
#define CONV_DIM (DSSM + 2*MS)          // 2176
#define PROJ_DIM (2*DSSM + 2*MS + MH)   // 4256
#define QKV_DIM (NH*HD + 2*NKV*HD)      // 3072
#define MROWS (B_*L_)                   // 2048

#define ATTN_IN 1.2f
#define ATTN_OUT 0.8f
#define KEY_MULT 0.7f
#define SSM_IN 1.1f
#define SSM_OUT 0.9f
#define GATE_MULT 0.9f
#define DOWN_MULT 0.8f
#define EPS_ 1e-5f

// ---------------- scratch (device globals; no allocation allowed) ----------------
__device__ float  g_proj[MROWS*PROJ_DIM];
__device__ float  g_conv[MROWS*CONV_DIM];
__device__ float  g_y   [MROWS*DSSM];
__device__ float  g_as  [MROWS*HID];
__device__ float  g_h   [MROWS*HID];

__device__ __half g_qkv16[MROWS*QKV_DIM];
__device__ __half g_gu16 [(size_t)MROWS*2*INTER];
__device__ __half g_hs16 [MROWS*HID];
__device__ __half g_ctx16[MROWS*HID];
__device__ __half g_gt16 [MROWS*DSSM];
__device__ __half g_hn16 [MROWS*HID];
__device__ __half g_act16[(size_t)MROWS*INTER];
__device__ __half g_q16  [MROWS*NH*HD];
__device__ __half g_k16  [B_*NKV*L_*HD];
__device__ __half g_v16t [B_*NKV*HD*L_];

// fp16 weights, one big buffer
#define W16_QKV     0
#define W16_INPROJ  (W16_QKV    + QKV_DIM*HID)
#define W16_O       (W16_INPROJ + PROJ_DIM*HID)
#define W16_OUTPROJ (W16_O      + HID*HID)
#define W16_GATEUP  (W16_OUTPROJ+ HID*DSSM)
#define W16_DOWN    (W16_GATEUP + 2*INTER*HID)
#define W16_TOTAL   (W16_DOWN   + HID*INTER)
__device__ __half g_w16[W16_TOTAL];

// ---------------- helpers ----------------
__device__ __forceinline__ float blockReduceSum256(float v) {
    __shared__ float sh[8];
    int lane = threadIdx.x & 31, w = threadIdx.x >> 5;
    #pragma unroll
    for (int o = 16; o; o >>= 1) v += __shfl_xor_sync(0xffffffffu, v, o);
    if (lane == 0) sh[w] = v;
    __syncthreads();
    v = (threadIdx.x < 8) ? sh[threadIdx.x] : 0.f;
    if (w == 0) {
        #pragma unroll
        for (int o = 4; o; o >>= 1) v += __shfl_xor_sync(0xffu, v, o);
    }
    return v;
}

__device__ __forceinline__ float siluf(float x) { return x / (1.f + __expf(-x)); }

__device__ __forceinline__ void mma_f16(float* c, const uint32_t* a, const uint32_t* b) {
    asm volatile(
        "mma.sync.aligned.m16n8k16.row.col.f32.f16.f16.f32 "
        "{%0,%1,%2,%3}, {%4,%5,%6,%7}, {%8,%9}, {%0,%1,%2,%3};"
        : "+f"(c[0]), "+f"(c[1]), "+f"(c[2]), "+f"(c[3])
        : "r"(a[0]), "r"(a[1]), "r"(a[2]), "r"(a[3]), "r"(b[0]), "r"(b[1]));
}

__device__ __forceinline__ uint32_t smem_u32(const void* p) {
    uint32_t a;
    asm("{ .reg .u64 t; cvta.to.shared.u64 t, %1; cvt.u32.u64 %0, t; }" : "=r"(a) : "l"(p));
    return a;
}
__device__ __forceinline__ void cp_async16(uint32_t dst, const void* src, int srcBytes) {
    asm volatile("cp.async.cg.shared.global [%0], [%1], 16, %2;"
                 :: "r"(dst), "l"(src), "r"(srcBytes));
}
#define CP_COMMIT() asm volatile("cp.async.commit_group;" ::: "memory")
#define CP_WAIT1()  asm volatile("cp.async.wait_group 1;"  ::: "memory")

__device__ __forceinline__ uint32_t packh2(float a, float b) {
    __half2 h = __floats2half2_rn(a, b);
    return *(uint32_t*)&h;
}

// ---------------- fp32 -> fp16 weight convert (coalesced, 1 float4/thread) -------
__global__ void cvt_f16_kernel(const float* __restrict__ in, __half* __restrict__ out, int n4) {
    int i = blockIdx.x*256 + threadIdx.x;
    if (i >= n4) return;
    float4 v = *(const float4*)(in + (size_t)i*4);
    *(uint2*)(out + (size_t)i*4) = make_uint2(packh2(v.x, v.y), packh2(v.z, v.w));
}

// ---------------- FP16 tensor-core GEMM (fp32 out, alpha/beta) ----------------
#define TBM 128
#define TBN 128
#define TBK 64
#define TSTP 36
#define STGP (128*TSTP)
#define GSMEM_BYTES (4*STGP*4)           // 73728 B

__global__ __launch_bounds__(256, 2) void gemm_f16(
    int Ni, int Ki, float alpha,
    const __half* __restrict__ A, const __half* __restrict__ Bw,
    float beta, const float* __restrict__ Cin, float* __restrict__ C)
{
    extern __shared__ uint32_t smp[];
    uint32_t* As[2] = { smp,          smp + 2*STGP };
    uint32_t* Bs[2] = { smp + STGP,   smp + 3*STGP };

    const int tid = threadIdx.x;
    const int bm = blockIdx.y * TBM, bn = blockIdx.x * TBN;
    const int warp = tid >> 5, lane = tid & 31;
    const int g = lane >> 2, t = lane & 3;
    const int wm = (warp >> 2) * 64;
    const int wn = (warp & 3) * 32;

    const int lrow = tid >> 3;
    const int lch  = tid & 7;

    const int nk = Ki / TBK;

    {
        #pragma unroll
        for (int q = 0; q < 4; ++q) {
            int row = lrow + q*32;
            cp_async16(smem_u32(As[0] + row*TSTP + lch*4),
                       A + (size_t)(bm + row)*Ki + lch*8, 16);
            int brow = bn + row;
            const __half* srcB = Bw + (size_t)(brow < Ni ? brow : 0)*Ki + lch*8;
            cp_async16(smem_u32(Bs[0] + row*TSTP + lch*4), srcB, brow < Ni ? 16 : 0);
        }
        CP_COMMIT();
    }

    float acc[4][4][4];
    #pragma unroll
    for (int i = 0; i < 4; ++i)
        #pragma unroll
        for (int j = 0; j < 4; ++j)
            #pragma unroll
            for (int r = 0; r < 4; ++r) acc[i][j][r] = 0.f;

    for (int j = 0; j < nk; ++j) {
        const int b = j & 1;
        if (j + 1 < nk) {
            const int k0 = (j + 1) * TBK;
            const int nb = b ^ 1;
            #pragma unroll
            for (int q = 0; q < 4; ++q) {
                int row = lrow + q*32;
                cp_async16(smem_u32(As[nb] + row*TSTP + lch*4),
                           A + (size_t)(bm + row)*Ki + k0 + lch*8, 16);
                int brow = bn + row;
                const __half* srcB = Bw + (size_t)(brow < Ni ? brow : 0)*Ki + k0 + lch*8;
                cp_async16(smem_u32(Bs[nb] + row*TSTP + lch*4), srcB, brow < Ni ? 16 : 0);
            }
        }
        CP_COMMIT();
        CP_WAIT1();
        __syncthreads();

        const uint32_t* as = As[b];
        const uint32_t* bs = Bs[b];
        #pragma unroll
        for (int ks = 0; ks < TBK/16; ++ks) {
            uint32_t af[4][4];
            #pragma unroll
            for (int i = 0; i < 4; ++i) {
                const uint32_t* r0 = as + (wm + i*16 + g)*TSTP + ks*8 + t;
                const uint32_t* r1 = r0 + 8*TSTP;
                af[i][0] = r0[0];
                af[i][1] = r1[0];
                af[i][2] = r0[4];
                af[i][3] = r1[4];
            }
            uint32_t bf[4][2];
            #pragma unroll
            for (int jj = 0; jj < 4; ++jj) {
                const uint32_t* base = bs + (wn + jj*8 + g)*TSTP + ks*8 + t;
                bf[jj][0] = base[0];
                bf[jj][1] = base[4];
            }
            #pragma unroll
            for (int i = 0; i < 4; ++i)
                #pragma unroll
                for (int jj = 0; jj < 4; ++jj)
                    mma_f16(acc[i][jj], af[i], bf[jj]);
        }
        __syncthreads();
    }

    #pragma unroll
    for (int i = 0; i < 4; ++i) {
        int row0 = bm + wm + i*16 + g;
        #pragma unroll
        for (int j = 0; j < 4; ++j) {
            int col = bn + wn + j*8 + 2*t;
            if (col >= Ni) continue;
            size_t o0 = (size_t)row0 * Ni + col;
            size_t o1 = (size_t)(row0 + 8) * Ni + col;
            float2 v0 = make_float2(alpha*acc[i][j][0], alpha*acc[i][j][1]);
            float2 v1 = make_float2(alpha*acc[i][j][2], alpha*acc[i][j][3]);
            if (beta != 0.f) {
                float2 e0 = *(const float2*)(Cin + o0);
                float2 e1 = *(const float2*)(Cin + o1);
                v0.x += beta*e0.x; v0.y += beta*e0.y;
                v1.x += beta*e1.x; v1.y += beta*e1.y;
            }
            *(float2*)(C + o0) = v0;
            *(float2*)(C + o1) = v1;
        }
    }
}

// ---------------- FP16 GEMM, fp16 output (alpha only) ----------------
__global__ __launch_bounds__(256, 2) void gemm_f16h(
    int Ni, int Ki, float alpha,
    const __half* __restrict__ A, const __half* __restrict__ Bw,
    __half* __restrict__ C)
{
    extern __shared__ uint32_t smp[];
    uint32_t* As[2] = { smp,          smp + 2*STGP };
    uint32_t* Bs[2] = { smp + STGP,   smp + 3*STGP };

    const int tid = threadIdx.x;
    const int bm = blockIdx.y * TBM, bn = blockIdx.x * TBN;
    const int warp = tid >> 5, lane = tid & 31;
    const int g = lane >> 2, t = lane & 3;
    const int wm = (warp >> 2) * 64;
    const int wn = (warp & 3) * 32;

    const int lrow = tid >> 3;
    const int lch  = tid & 7;

    const int nk = Ki / TBK;

    {
        #pragma unroll
        for (int q = 0; q < 4; ++q) {
            int row = lrow + q*32;
            cp_async16(smem_u32(As[0] + row*TSTP + lch*4),
                       A + (size_t)(bm + row)*Ki + lch*8, 16);
            int brow = bn + row;
            const __half* srcB = Bw + (size_t)(brow < Ni ? brow : 0)*Ki + lch*8;
            cp_async16(smem_u32(Bs[0] + row*TSTP + lch*4), srcB, brow < Ni ? 16 : 0);
        }
        CP_COMMIT();
    }

    float acc[4][4][4];
    #pragma unroll
    for (int i = 0; i < 4; ++i)
        #pragma unroll
        for (int j = 0; j < 4; ++j)
            #pragma unroll
            for (int r = 0; r < 4; ++r) acc[i][j][r] = 0.f;

    for (int j = 0; j < nk; ++j) {
        const int b = j & 1;
        if (j + 1 < nk) {
            const int k0 = (j + 1) * TBK;
            const int nb = b ^ 1;
            #pragma unroll
            for (int q = 0; q < 4; ++q) {
                int row = lrow + q*32;
                cp_async16(smem_u32(As[nb] + row*TSTP + lch*4),
                           A + (size_t)(bm + row)*Ki + k0 + lch*8, 16);
                int brow = bn + row;
                const __half* srcB = Bw + (size_t)(brow < Ni ? brow : 0)*Ki + k0 + lch*8;
                cp_async16(smem_u32(Bs[nb] + row*TSTP + lch*4), srcB, brow < Ni ? 16 : 0);
            }
        }
        CP_COMMIT();
        CP_WAIT1();
        __syncthreads();

        const uint32_t* as = As[b];
        const uint32_t* bs = Bs[b];
        #pragma unroll
        for (int ks = 0; ks < TBK/16; ++ks) {
            uint32_t af[4][4];
            #pragma unroll
            for (int i = 0; i < 4; ++i) {
                const uint32_t* r0 = as + (wm + i*16 + g)*TSTP + ks*8 + t;
                const uint32_t* r1 = r0 + 8*TSTP;
                af[i][0] = r0[0];
                af[i][1] = r1[0];
                af[i][2] = r0[4];
                af[i][3] = r1[4];
            }
            uint32_t bf[4][2];
            #pragma unroll
            for (int jj = 0; jj < 4; ++jj) {
                const uint32_t* base = bs + (wn + jj*8 + g)*TSTP + ks*8 + t;
                bf[jj][0] = base[0];
                bf[jj][1] = base[4];
            }
            #pragma unroll
            for (int i = 0; i < 4; ++i)
                #pragma unroll
                for (int jj = 0; jj < 4; ++jj)
                    mma_f16(acc[i][jj], af[i], bf[jj]);
        }
        __syncthreads();
    }

    #pragma unroll
    for (int i = 0; i < 4; ++i) {
        int row0 = bm + wm + i*16 + g;
        #pragma unroll
        for (int j = 0; j < 4; ++j) {
            int col = bn + wn + j*8 + 2*t;
            if (col >= Ni) continue;
            *(uint32_t*)(C + (size_t)row0 * Ni + col) =
                packh2(alpha*acc[i][j][0], alpha*acc[i][j][1]);
            *(uint32_t*)(C + (size_t)(row0 + 8) * Ni + col) =
                packh2(alpha*acc[i][j][2], alpha*acc[i][j][3]);
        }
    }
}

// ---------------- RMS norm: hs16 = f16(rms(x)*w) ----------------
__global__ __launch_bounds__(256) void rms_kernel(
    const float* __restrict__ x, const float* __restrict__ w, __half* __restrict__ out)
{
    int m = blockIdx.x;
    const float* xr = x + (size_t)m * HID;
    float v[8]; float ss = 0.f;
    #pragma unroll
    for (int k = 0; k < 8; ++k) { v[k] = xr[threadIdx.x + k*256]; ss += v[k]*v[k]; }
    ss = blockReduceSum256(ss);
    __shared__ float s_inv;
    if (threadIdx.x == 0) s_inv = rsqrtf(ss * (1.f/HID) + EPS_);
    __syncthreads();
    float inv = s_inv;
    __half* o = out + (size_t)m * HID;
    #pragma unroll
    for (int k = 0; k < 8; ++k) { int c = threadIdx.x + k*256; o[c] = __float2half_rn(v[k]*inv*w[c]); }
}

// ---------------- RoPE on fp16 qkv -> fp16 q (x1/8) and k (head-major) ----------
__global__ void rope_kernel(const __half* __restrict__ qkv, const int* __restrict__ positions,
                            __half* __restrict__ q16, __half* __restrict__ k16) {
    int idx = blockIdx.x*256 + threadIdx.x;
    const int total = MROWS*(NH+NKV)*32;
    if (idx >= total) return;
    int i = idx & 31; int rest = idx >> 5;
    int head = rest % (NH+NKV); int ml = rest / (NH+NKV);
    int l = ml % L_, b = ml / L_;
    float inv = powf(1e11f, -(float)i/32.0f);
    float ang = (float)positions[l] * inv;
    float c = cosf(ang), s = sinf(ang);
    if (head < NH) {
        const __half* p = qkv + (size_t)ml*QKV_DIM + head*HD;
        float x1 = __half2float(p[i]), x2 = __half2float(p[i+32]);
        __half* o = q16 + (size_t)ml*(NH*HD) + head*HD;
        o[i]    = __float2half_rn((x1*c - x2*s) * 0.125f);
        o[i+32] = __float2half_rn((x2*c + x1*s) * 0.125f);
    } else {
        int g = head - NH;
        const __half* p = qkv + (size_t)ml*QKV_DIM + NH*HD + g*HD;
        float x1 = __half2float(p[i])*KEY_MULT, x2 = __half2float(p[i+32])*KEY_MULT;
        __half* o = k16 + ((size_t)(b*NKV + g)*L_ + l)*HD;
        o[i]    = __float2half_rn(x1*c - x2*s);
        o[i+32] = __float2half_rn(x2*c + x1*s);
    }
}

// ---------------- V transpose: fp16 qkv v-part -> v16t [b][g][d][L] --------------
__global__ __launch_bounds__(256) void vtrans_kernel(
    const __half* __restrict__ qkv, __half* __restrict__ v16t)
{
    __shared__ __half ts[64][65];
    const int lt = blockIdx.x, g = blockIdx.y, b = blockIdx.z;
    const int vcol = NH*HD + NKV*HD + g*HD;
    const int tid = threadIdx.x;
    #pragma unroll
    for (int q = 0; q < 16; ++q) {
        int idx = tid + q*256;
        int row = idx >> 6, col = idx & 63;
        ts[col][row] = qkv[(size_t)(b*L_ + lt*64 + row)*QKV_DIM + vcol + col];
    }
    __syncthreads();
    #pragma unroll
    for (int q = 0; q < 16; ++q) {
        int idx = tid + q*256;
        int d = idx >> 6, l = idx & 63;
        v16t[((size_t)(b*NKV + g)*HD + d)*L_ + lt*64 + l] = ts[d][l];
    }
}

// ---------------- tensor-core flash attention (causal, GQA, HD=64) --------------
__global__ __launch_bounds__(128) void attn_kernel(
    const __half* __restrict__ q16, const __half* __restrict__ k16,
    const __half* __restrict__ v16t, __half* __restrict__ ctx)
{
    __shared__ uint32_t Qs[64*36];
    __shared__ uint32_t Ks[64*36];
    __shared__ uint32_t Vs[64*36];
    const int tid = threadIdx.x;
    const int warp = tid >> 5, lane = tid & 31;
    const int g = lane >> 2, t = lane & 3;
    const int wm = warp*16;
    const int qb = blockIdx.x, h = blockIdx.y, b = blockIdx.z;
    const int kg = h >> 2;

    {
        const __half* qp = q16 + (size_t)(b*L_ + qb*64)*(NH*HD) + h*HD;
        #pragma unroll
        for (int q = 0; q < 4; ++q) {
            int idx = tid + q*128;
            int row = idx >> 3, ch = idx & 7;
            *(uint4*)(&Qs[row*36 + ch*4]) =
                *(const uint4*)(qp + (size_t)row*(NH*HD) + ch*8);
        }
    }
    __syncthreads();

    uint32_t aq[4][4];
    #pragma unroll
    for (int ks = 0; ks < 4; ++ks) {
        const uint32_t* r0 = Qs + (wm + g)*36 + ks*8 + t;
        const uint32_t* r1 = Qs + (wm + g + 8)*36 + ks*8 + t;
        aq[ks][0] = r0[0]; aq[ks][1] = r1[0]; aq[ks][2] = r0[4]; aq[ks][3] = r1[4];
    }

    float oacc[8][4];
    #pragma unroll
    for (int jj = 0; jj < 8; ++jj)
        #pragma unroll
        for (int r = 0; r < 4; ++r) oacc[jj][r] = 0.f;
    float m_a = -1e30f, m_b = -1e30f, l_a = 0.f, l_b = 0.f;

    const __half* kp = k16 + (size_t)(b*NKV + kg)*L_*HD;
    const __half* vp = v16t + (size_t)(b*NKV + kg)*HD*L_;

    for (int j = 0; j <= qb; ++j) {
        __syncthreads();
        #pragma unroll
        for (int q = 0; q < 4; ++q) {
            int idx = tid + q*128;
            int row = idx >> 3, ch = idx & 7;
            *(uint4*)(&Ks[row*36 + ch*4]) =
                *(const uint4*)(kp + (size_t)(j*64 + row)*HD + ch*8);
            *(uint4*)(&Vs[row*36 + ch*4]) =
                *(const uint4*)(vp + (size_t)row*L_ + j*64 + ch*8);
        }
        __syncthreads();

        float sacc[8][4];
        #pragma unroll
        for (int jj = 0; jj < 8; ++jj)
            #pragma unroll
            for (int r = 0; r < 4; ++r) sacc[jj][r] = 0.f;
        #pragma unroll
        for (int ks = 0; ks < 4; ++ks) {
            #pragma unroll
            for (int jj = 0; jj < 8; ++jj) {
                uint32_t bk[2];
                const uint32_t* base = Ks + (jj*8 + g)*36 + ks*8 + t;
                bk[0] = base[0]; bk[1] = base[4];
                mma_f16(sacc[jj], aq[ks], bk);
            }
        }

        if (j == qb) {
            const int ra = wm + g, rb = ra + 8;
            #pragma unroll
            for (int jj = 0; jj < 8; ++jj) {
                int c0 = jj*8 + 2*t, c1 = c0 + 1;
                if (c0 > ra) sacc[jj][0] = -1e30f;
                if (c1 > ra) sacc[jj][1] = -1e30f;
                if (c0 > rb) sacc[jj][2] = -1e30f;
                if (c1 > rb) sacc[jj][3] = -1e30f;
            }
        }

        float mx_a = -1e30f, mx_b = -1e30f;
        #pragma unroll
        for (int jj = 0; jj < 8; ++jj) {
            mx_a = fmaxf(mx_a, fmaxf(sacc[jj][0], sacc[jj][1]));
            mx_b = fmaxf(mx_b, fmaxf(sacc[jj][2], sacc[jj][3]));
        }
        mx_a = fmaxf(mx_a, __shfl_xor_sync(0xffffffffu, mx_a, 1));
        mx_a = fmaxf(mx_a, __shfl_xor_sync(0xffffffffu, mx_a, 2));
        mx_b = fmaxf(mx_b, __shfl_xor_sync(0xffffffffu, mx_b, 1));
        mx_b = fmaxf(mx_b, __shfl_xor_sync(0xffffffffu, mx_b, 2));
        float mna = fmaxf(m_a, mx_a), mnb = fmaxf(m_b, mx_b);
        float ca = __expf(m_a - mna), cb = __expf(m_b - mnb);
        m_a = mna; m_b = mnb;
        float sa = 0.f, sb = 0.f;
        #pragma unroll
        for (int jj = 0; jj < 8; ++jj) {
            sacc[jj][0] = __expf(sacc[jj][0] - mna);
            sacc[jj][1] = __expf(sacc[jj][1] - mna);
            sacc[jj][2] = __expf(sacc[jj][2] - mnb);
            sacc[jj][3] = __expf(sacc[jj][3] - mnb);
            sa += sacc[jj][0] + sacc[jj][1];
            sb += sacc[jj][2] + sacc[jj][3];
        }
        sa += __shfl_xor_sync(0xffffffffu, sa, 1);
        sa += __shfl_xor_sync(0xffffffffu, sa, 2);
        sb += __shfl_xor_sync(0xffffffffu, sb, 1);
        sb += __shfl_xor_sync(0xffffffffu, sb, 2);
        l_a = l_a*ca + sa; l_b = l_b*cb + sb;
        #pragma unroll
        for (int jj = 0; jj < 8; ++jj) {
            oacc[jj][0] *= ca; oacc[jj][1] *= ca;
            oacc[jj][2] *= cb; oacc[jj][3] *= cb;
        }

        uint32_t aP[4][4];
        #pragma unroll
        for (int s = 0; s < 4; ++s) {
            aP[s][0] = packh2(sacc[2*s][0],   sacc[2*s][1]);
            aP[s][1] = packh2(sacc[2*s][2],   sacc[2*s][3]);
            aP[s][2] = packh2(sacc[2*s+1][0], sacc[2*s+1][1]);
            aP[s][3] = packh2(sacc[2*s+1][2], sacc[2*s+1][3]);
        }

        #pragma unroll
        for (int s = 0; s < 4; ++s) {
            #pragma unroll
            for (int jj = 0; jj < 8; ++jj) {
                uint32_t bv[2];
                const uint32_t* base = Vs + (jj*8 + g)*36 + s*8 + t;
                bv[0] = base[0]; bv[1] = base[4];
                mma_f16(oacc[jj], aP[s], bv);
            }
        }
    }

    float ila = 1.f / l_a, ilb = 1.f / l_b;
    int ra = qb*64 + wm + g;
    __half* op = ctx + (size_t)(b*L_ + ra)*HID + h*HD + 2*t;
    #pragma unroll
    for (int jj = 0; jj < 8; ++jj) {
        *(uint32_t*)(op + jj*8) = packh2(oacc[jj][0]*ila, oacc[jj][1]*ila);
        *(uint32_t*)(op + 8*HID + jj*8) = packh2(oacc[jj][2]*ilb, oacc[jj][3]*ilb);
    }
}

// ---------------- depthwise causal conv (MK=4) + mup + bias + SiLU ----------------
__global__ void conv_kernel(const float* __restrict__ proj, const float* __restrict__ cw,
                            const float* __restrict__ cb, float* __restrict__ out)
{
    int idx = blockIdx.x*256 + threadIdx.x;
    if (idx >= MROWS*CONV_DIM) return;
    int c = idx % CONV_DIM;
    int ml = idx / CONV_DIM;
    int l = ml % L_, b = ml / L_;
    float mupf = (c < DSSM) ? 0.9f : ((c < DSSM+MS) ? 0.8f : 1.1f);
    float s = 0.f;
    #pragma unroll
    for (int k = 0; k < MK; ++k) {
        int ls = l + k - (MK-1);
        if (ls >= 0) s += proj[(size_t)(b*L_+ls)*PROJ_DIM + DSSM + c] * cw[c*MK + k];
    }
    s = mupf*s + cb[c];
    out[idx] = siluf(s);
}

// ---------------- Mamba2 selective scan ----------------
#define SCT 32
__global__ __launch_bounds__(256) void scan_kernel(
    const float* __restrict__ conv, const float* __restrict__ proj,
    const float* __restrict__ A_log, const float* __restrict__ dt_bias,
    const float* __restrict__ Dp, float* __restrict__ y)
{
    const int b = blockIdx.x / MH, h = blockIdx.x % MH;
    const int tid = threadIdx.x;
    const int p = tid >> 2, sg = tid & 3, s0 = sg*16;
    const float Ah = -__expf(A_log[h]);
    const float Dh = Dp[h];
    const float dtb = dt_bias[h];
    float st[16];
    #pragma unroll
    for (int i = 0; i < 16; ++i) st[i] = 0.f;

    __shared__ float xs[SCT][64], Bsh[SCT][64], Csh[SCT][64], dts[SCT];

    for (int l0 = 0; l0 < L_; l0 += SCT) {
        __syncthreads();
        for (int i = tid; i < SCT*64; i += 256) {
            int t = i >> 6, c = i & 63;
            size_t base = (size_t)(b*L_ + l0 + t)*CONV_DIM;
            xs[t][c]  = conv[base + h*64 + c];
            Bsh[t][c] = conv[base + DSSM + c];
            Csh[t][c] = conv[base + DSSM + MS + c];
        }
        for (int i = tid; i < SCT; i += 256) {
            float r = proj[(size_t)(b*L_ + l0 + i)*PROJ_DIM + (PROJ_DIM-MH) + h] * 1.2f + dtb;
            dts[i] = (r > 20.f) ? r : log1pf(expf(r));   // softplus
        }
        __syncthreads();
        for (int t = 0; t < SCT; ++t) {
            float dt = dts[t];
            float dA = __expf(dt * Ah);
            float xv = xs[t][p];
            float coef = dt * xv;
            float acc = 0.f;
            #pragma unroll
            for (int ss = 0; ss < 16; ++ss) {
                st[ss] = st[ss]*dA + coef*Bsh[t][s0+ss];
                acc = fmaf(st[ss], Csh[t][s0+ss], acc);
            }
            acc += __shfl_xor_sync(0xffffffffu, acc, 1);
            acc += __shfl_xor_sync(0xffffffffu, acc, 2);
            if (sg == 0)
                y[(size_t)(b*L_ + l0 + t)*DSSM + h*64 + p] = acc + xv*Dh;
        }
    }
}

// ---------------- gating + RMS -> fp16 ----------------
__global__ __launch_bounds__(256) void gate_rms_kernel(
    const float* __restrict__ y, const float* __restrict__ proj,
    const float* __restrict__ w, __half* __restrict__ out)
{
    int m = blockIdx.x;
    const float* yr = y + (size_t)m*DSSM;
    const float* zr = proj + (size_t)m*PROJ_DIM;
    float v[8]; float ss = 0.f;
    #pragma unroll
    for (int k = 0; k < 8; ++k) {
        int c = threadIdx.x + k*256;
        float z = zr[c];
        float gv = yr[c] * siluf(z);
        v[k] = gv; ss += gv*gv;
    }
    ss = blockReduceSum256(ss);
    __shared__ float s_inv;
    if (threadIdx.x == 0) s_inv = rsqrtf(ss * (1.f/DSSM) + EPS_);
    __syncthreads();
    float inv = s_inv;
    __half* o = out + (size_t)m*DSSM;
    #pragma unroll
    for (int k = 0; k < 8; ++k) { int c = threadIdx.x + k*256; o[c] = __float2half_rn(v[k]*inv*w[c]); }
}

// ---------------- combine: h = as + residual ; hn16 = f16(rms(h)*w) ----------------
__global__ __launch_bounds__(256) void combine_kernel(
    const float* __restrict__ as_, const float* __restrict__ resid,
    const float* __restrict__ w, float* __restrict__ h, __half* __restrict__ hn)
{
    int m = blockIdx.x;
    const float* ar = as_  + (size_t)m*HID;
    const float* rr = resid + (size_t)m*HID;
    float v[8]; float ss = 0.f;
    #pragma unroll
    for (int k = 0; k < 8; ++k) {
        int c = threadIdx.x + k*256;
        float hv = ar[c] + rr[c];
        v[k] = hv; ss += hv*hv;
    }
    ss = blockReduceSum256(ss);
    __shared__ float s_inv;
    if (threadIdx.x == 0) s_inv = rsqrtf(ss * (1.f/HID) + EPS_);
    __syncthreads();
    float inv = s_inv;
    float* ho = h + (size_t)m*HID;
    __half* no = hn + (size_t)m*HID;
    #pragma unroll
    for (int k = 0; k < 8; ++k) {
        int c = threadIdx.x + k*256;
        ho[c] = v[k];
        no[c] = __float2half_rn(v[k]*inv*w[c]);
    }
}

// ---------------- SwiGLU activation on fp16 gu -> fp16 ----------------
__global__ void act_kernel(const __half* __restrict__ gu, __half* __restrict__ act) {
    int idx = blockIdx.x*256 + threadIdx.x;
    if (idx >= MROWS*INTER/2) return;
    int m = idx / (INTER/2);
    int i = (idx % (INTER/2)) * 2;
    const __half* row = gu + (size_t)m*(2*INTER);
    __half2 g2 = *(const __half2*)(row + i);
    __half2 u2 = *(const __half2*)(row + INTER + i);
    float g0 = __half2float(g2.x) * GATE_MULT;
    float g1 = __half2float(g2.y) * GATE_MULT;
    float a0 = siluf(g0) * __half2float(u2.x);
    float a1 = siluf(g1) * __half2float(u2.y);
    *(uint32_t*)(act + (size_t)m*INTER + i) = packh2(a0, a1);
}

// ---------------- host launcher ----------------
extern "C" void kernel_launch(void* const* d_in, const int* in_sizes, int n_in,
                              void* d_out, int out_size)
{
    const float* hidden      = (const float*)d_in[0];
    const int*   positions   = (const int*)  d_in[1];
    const float* w_in_ln     = (const float*)d_in[2];
    const float* qkv_w       = (const float*)d_in[3];
    const float* o_w         = (const float*)d_in[4];
    const float* in_proj_w   = (const float*)d_in[5];
    const float* conv_w      = (const float*)d_in[6];
    const float* conv_b      = (const float*)d_in[7];
    const float* A_log       = (const float*)d_in[8];
    const float* dt_bias     = (const float*)d_in[9];
    const float* Dp          = (const float*)d_in[10];
    const float* ssm_norm_w  = (const float*)d_in[11];
    const float* out_proj_w  = (const float*)d_in[12];
    const float* w_pre_ff_ln = (const float*)d_in[13];
    const float* gate_up_w   = (const float*)d_in[14];
    const float* down_w      = (const float*)d_in[15];
    float* out = (float*)d_out;

    float *proj, *conv, *y, *as_, *h;
    __half *qkv16, *gu16, *hs16, *ctx16, *gt16, *hn16, *act16, *w16, *q16, *k16, *v16t;
    cudaGetSymbolAddress((void**)&proj, g_proj);
    cudaGetSymbolAddress((void**)&conv, g_conv);
    cudaGetSymbolAddress((void**)&y,    g_y);
    cudaGetSymbolAddress((void**)&as_,  g_as);
    cudaGetSymbolAddress((void**)&h,    g_h);
    cudaGetSymbolAddress((void**)&qkv16,g_qkv16);
    cudaGetSymbolAddress((void**)&gu16, g_gu16);
    cudaGetSymbolAddress((void**)&hs16, g_hs16);
    cudaGetSymbolAddress((void**)&ctx16,g_ctx16);
    cudaGetSymbolAddress((void**)&gt16, g_gt16);
    cudaGetSymbolAddress((void**)&hn16, g_hn16);
    cudaGetSymbolAddress((void**)&act16,g_act16);
    cudaGetSymbolAddress((void**)&w16,  g_w16);
    cudaGetSymbolAddress((void**)&q16,  g_q16);
    cudaGetSymbolAddress((void**)&k16,  g_k16);
    cudaGetSymbolAddress((void**)&v16t, g_v16t);

    cudaFuncSetAttribute(gemm_f16,  cudaFuncAttributeMaxDynamicSharedMemorySize, GSMEM_BYTES);
    cudaFuncSetAttribute(gemm_f16h, cudaFuncAttributeMaxDynamicSharedMemorySize, GSMEM_BYTES);

    const int MT = MROWS/TBM;   // 16

    // 0. weight conversion fp32 -> fp16 (coalesced)
    #define CVT(src, dstoff, n) \
        cvt_f16_kernel<<<((n)/4 + 255)/256, 256>>>(src, w16 + (size_t)(dstoff), (n)/4)
    CVT(qkv_w,      W16_QKV,     QKV_DIM*HID);
    CVT(in_proj_w,  W16_INPROJ,  PROJ_DIM*HID);
    CVT(o_w,        W16_O,       HID*HID);
    CVT(out_proj_w, W16_OUTPROJ, HID*DSSM);
    CVT(gate_up_w,  W16_GATEUP,  2*INTER*HID);
    CVT(down_w,     W16_DOWN,    HID*INTER);
    #undef CVT

    // 1. input RMS norm (fp16 out)
    rms_kernel<<<MROWS, 256>>>(hidden, w_in_ln, hs16);

    // 2. qkv (fp16 out) ; proj (fp32)
    gemm_f16h<<<dim3(QKV_DIM/TBN, MT), 256, GSMEM_BYTES>>>(QKV_DIM, HID, ATTN_IN,
                                            hs16, w16 + W16_QKV, qkv16);
    gemm_f16<<<dim3((PROJ_DIM+TBN-1)/TBN, MT), 256, GSMEM_BYTES>>>(PROJ_DIM, HID, SSM_IN,
                                            hs16, w16 + W16_INPROJ, 0.f, nullptr, proj);

    // 3. RoPE -> fp16 q/k ; V transpose -> fp16
    rope_kernel<<<(MROWS*(NH+NKV)*32 + 255)/256, 256>>>(qkv16, positions, q16, k16);
    vtrans_kernel<<<dim3(L_/64, NKV, B_), 256>>>(qkv16, v16t);

    // 4. tensor-core flash attention (fp16 ctx out)
    attn_kernel<<<dim3(L_/64, NH, B_), 128>>>(q16, k16, v16t, ctx16);

    // 5. as = ATTN_OUT * ctx @ o_w^T
    gemm_f16<<<dim3(HID/TBN, MT), 256, GSMEM_BYTES>>>(HID, HID, ATTN_OUT,
                                            ctx16, w16 + W16_O, 0.f, nullptr, as_);

    // 6. mamba: conv -> scan -> gate+rms -> out_proj (accumulate into as)
    conv_kernel<<<(MROWS*CONV_DIM + 255)/256, 256>>>(proj, conv_w, conv_b, conv);
    scan_kernel<<<B_*MH, 256>>>(conv, proj, A_log, dt_bias, Dp, y);
    gate_rms_kernel<<<MROWS, 256>>>(y, proj, ssm_norm_w, gt16);
    gemm_f16<<<dim3(HID/TBN, MT), 256, GSMEM_BYTES>>>(HID, DSSM, SSM_OUT,
                                            gt16, w16 + W16_OUTPROJ, 1.f, as_, as_);

    // 7. combine + pre-FF RMS (fp16 hn out)
    combine_kernel<<<MROWS, 256>>>(as_, hidden, w_pre_ff_ln, h, hn16);

    // 8. MLP: gate_up (fp16 gu) -> act -> down
    gemm_f16h<<<dim3(2*INTER/TBN, MT), 256, GSMEM_BYTES>>>(2*INTER, HID, 1.f,
                                            hn16, w16 + W16_GATEUP, gu16);
    act_kernel<<<(MROWS*INTER/2 + 255)/256, 256>>>(gu16, act16);
    gemm_f16<<<dim3(HID/TBN, MT), 256, GSMEM_BYTES>>>(HID, INTER, DOWN_MULT,
                                            act16, w16 + W16_DOWN, 1.f, h, out);
    (void)in_sizes; (void)n_in; (void)out_size;
}

// round 14
// speedup vs baseline: 1.2871x; 1.0573x over previous
#include <cuda_runtime.h>
#include <cuda_fp16.h>
#include <math.h>
#include <stdint.h>

#define B_ 2
#define L_ 1024
#define HID 2048
#define NH 32
#define HD 64
#define NKV 8
#define INTER 8192
#define DSSM 2048
#define MH 32
#define MP 64
#define MS 64
#define MK 4
#define CONV_DIM (DSSM + 2*MS)          // 2176
#define PROJ_DIM (2*DSSM + 2*MS + MH)   // 4256
#define QKV_DIM (NH*HD + 2*NKV*HD)      // 3072
#define MROWS (B_*L_)                   // 2048

#define ATTN_IN 1.2f
#define ATTN_OUT 0.8f
#define KEY_MULT 0.7f
#define SSM_IN 1.1f
#define SSM_OUT 0.9f
#define GATE_MULT 0.9f
#define DOWN_MULT 0.8f
#define EPS_ 1e-5f

// ---------------- scratch (device globals; no allocation allowed) ----------------
__device__ float  g_proj[MROWS*PROJ_DIM];
__device__ float  g_conv[MROWS*CONV_DIM];
__device__ float  g_y   [MROWS*DSSM];
__device__ float  g_as  [MROWS*HID];
__device__ float  g_h   [MROWS*HID];

__device__ __half g_qkv16[MROWS*QKV_DIM];
__device__ __half g_gu16 [(size_t)MROWS*2*INTER];
__device__ __half g_hs16 [MROWS*HID];
__device__ __half g_ctx16[MROWS*HID];
__device__ __half g_gt16 [MROWS*DSSM];
__device__ __half g_hn16 [MROWS*HID];
__device__ __half g_act16[(size_t)MROWS*INTER];
__device__ __half g_q16  [MROWS*NH*HD];
__device__ __half g_k16  [B_*NKV*L_*HD];
__device__ __half g_v16t [B_*NKV*HD*L_];

// fp16 weights, one big buffer
#define W16_QKV     0
#define W16_INPROJ  (W16_QKV    + QKV_DIM*HID)
#define W16_O       (W16_INPROJ + PROJ_DIM*HID)
#define W16_OUTPROJ (W16_O      + HID*HID)
#define W16_GATEUP  (W16_OUTPROJ+ HID*DSSM)
#define W16_DOWN    (W16_GATEUP + 2*INTER*HID)
#define W16_TOTAL   (W16_DOWN   + HID*INTER)
__device__ __half g_w16[W16_TOTAL];

// ---------------- helpers ----------------
__device__ __forceinline__ float blockReduceSum256(float v) {
    __shared__ float sh[8];
    int lane = threadIdx.x & 31, w = threadIdx.x >> 5;
    #pragma unroll
    for (int o = 16; o; o >>= 1) v += __shfl_xor_sync(0xffffffffu, v, o);
    if (lane == 0) sh[w] = v;
    __syncthreads();
    v = (threadIdx.x < 8) ? sh[threadIdx.x] : 0.f;
    if (w == 0) {
        #pragma unroll
        for (int o = 4; o; o >>= 1) v += __shfl_xor_sync(0xffu, v, o);
    }
    return v;
}

__device__ __forceinline__ float siluf(float x) { return x / (1.f + __expf(-x)); }

__device__ __forceinline__ void mma_f16(float* c, const uint32_t* a, const uint32_t* b) {
    asm volatile(
        "mma.sync.aligned.m16n8k16.row.col.f32.f16.f16.f32 "
        "{%0,%1,%2,%3}, {%4,%5,%6,%7}, {%8,%9}, {%0,%1,%2,%3};"
        : "+f"(c[0]), "+f"(c[1]), "+f"(c[2]), "+f"(c[3])
        : "r"(a[0]), "r"(a[1]), "r"(a[2]), "r"(a[3]), "r"(b[0]), "r"(b[1]));
}

__device__ __forceinline__ uint32_t smem_u32(const void* p) {
    uint32_t a;
    asm("{ .reg .u64 t; cvta.to.shared.u64 t, %1; cvt.u32.u64 %0, t; }" : "=r"(a) : "l"(p));
    return a;
}
__device__ __forceinline__ void cp_async16(uint32_t dst, const void* src, int srcBytes) {
    asm volatile("cp.async.cg.shared.global [%0], [%1], 16, %2;"
                 :: "r"(dst), "l"(src), "r"(srcBytes));
}
#define CP_COMMIT() asm volatile("cp.async.commit_group;" ::: "memory")
#define CP_WAIT1()  asm volatile("cp.async.wait_group 1;"  ::: "memory")

__device__ __forceinline__ uint32_t packh2(float a, float b) {
    __half2 h = __floats2half2_rn(a, b);
    return *(uint32_t*)&h;
}

// ---------------- fp32 -> fp16 weight convert (coalesced, 1 float4/thread) -------
__global__ void cvt_f16_kernel(const float* __restrict__ in, __half* __restrict__ out, int n4) {
    int i = blockIdx.x*256 + threadIdx.x;
    if (i >= n4) return;
    float4 v = *(const float4*)(in + (size_t)i*4);
    *(uint2*)(out + (size_t)i*4) = make_uint2(packh2(v.x, v.y), packh2(v.z, v.w));
}

// ---------------- FP16 tensor-core GEMM (fp32 out, alpha/beta) ----------------
#define TBM 128
#define TBN 128
#define TBK 64
#define TSTP 36
#define STGP (128*TSTP)
#define GSMEM_BYTES (4*STGP*4)           // 73728 B

__global__ __launch_bounds__(256, 2) void gemm_f16(
    int Ni, int Ki, float alpha,
    const __half* __restrict__ A, const __half* __restrict__ Bw,
    float beta, const float* __restrict__ Cin, float* __restrict__ C)
{
    extern __shared__ uint32_t smp[];
    uint32_t* As[2] = { smp,          smp + 2*STGP };
    uint32_t* Bs[2] = { smp + STGP,   smp + 3*STGP };

    const int tid = threadIdx.x;
    const int bm = blockIdx.y * TBM, bn = blockIdx.x * TBN;
    const int warp = tid >> 5, lane = tid & 31;
    const int g = lane >> 2, t = lane & 3;
    const int wm = (warp >> 2) * 64;
    const int wn = (warp & 3) * 32;

    const int lrow = tid >> 3;
    const int lch  = tid & 7;

    const int nk = Ki / TBK;

    {
        #pragma unroll
        for (int q = 0; q < 4; ++q) {
            int row = lrow + q*32;
            cp_async16(smem_u32(As[0] + row*TSTP + lch*4),
                       A + (size_t)(bm + row)*Ki + lch*8, 16);
            int brow = bn + row;
            const __half* srcB = Bw + (size_t)(brow < Ni ? brow : 0)*Ki + lch*8;
            cp_async16(smem_u32(Bs[0] + row*TSTP + lch*4), srcB, brow < Ni ? 16 : 0);
        }
        CP_COMMIT();
    }

    float acc[4][4][4];
    #pragma unroll
    for (int i = 0; i < 4; ++i)
        #pragma unroll
        for (int j = 0; j < 4; ++j)
            #pragma unroll
            for (int r = 0; r < 4; ++r) acc[i][j][r] = 0.f;

    for (int j = 0; j < nk; ++j) {
        const int b = j & 1;
        if (j + 1 < nk) {
            const int k0 = (j + 1) * TBK;
            const int nb = b ^ 1;
            #pragma unroll
            for (int q = 0; q < 4; ++q) {
                int row = lrow + q*32;
                cp_async16(smem_u32(As[nb] + row*TSTP + lch*4),
                           A + (size_t)(bm + row)*Ki + k0 + lch*8, 16);
                int brow = bn + row;
                const __half* srcB = Bw + (size_t)(brow < Ni ? brow : 0)*Ki + k0 + lch*8;
                cp_async16(smem_u32(Bs[nb] + row*TSTP + lch*4), srcB, brow < Ni ? 16 : 0);
            }
        }
        CP_COMMIT();
        CP_WAIT1();
        __syncthreads();

        const uint32_t* as = As[b];
        const uint32_t* bs = Bs[b];
        #pragma unroll
        for (int ks = 0; ks < TBK/16; ++ks) {
            uint32_t af[4][4];
            #pragma unroll
            for (int i = 0; i < 4; ++i) {
                const uint32_t* r0 = as + (wm + i*16 + g)*TSTP + ks*8 + t;
                const uint32_t* r1 = r0 + 8*TSTP;
                af[i][0] = r0[0];
                af[i][1] = r1[0];
                af[i][2] = r0[4];
                af[i][3] = r1[4];
            }
            uint32_t bf[4][2];
            #pragma unroll
            for (int jj = 0; jj < 4; ++jj) {
                const uint32_t* base = bs + (wn + jj*8 + g)*TSTP + ks*8 + t;
                bf[jj][0] = base[0];
                bf[jj][1] = base[4];
            }
            #pragma unroll
            for (int i = 0; i < 4; ++i)
                #pragma unroll
                for (int jj = 0; jj < 4; ++jj)
                    mma_f16(acc[i][jj], af[i], bf[jj]);
        }
        __syncthreads();
    }

    #pragma unroll
    for (int i = 0; i < 4; ++i) {
        int row0 = bm + wm + i*16 + g;
        #pragma unroll
        for (int j = 0; j < 4; ++j) {
            int col = bn + wn + j*8 + 2*t;
            if (col >= Ni) continue;
            size_t o0 = (size_t)row0 * Ni + col;
            size_t o1 = (size_t)(row0 + 8) * Ni + col;
            float2 v0 = make_float2(alpha*acc[i][j][0], alpha*acc[i][j][1]);
            float2 v1 = make_float2(alpha*acc[i][j][2], alpha*acc[i][j][3]);
            if (beta != 0.f) {
                float2 e0 = *(const float2*)(Cin + o0);
                float2 e1 = *(const float2*)(Cin + o1);
                v0.x += beta*e0.x; v0.y += beta*e0.y;
                v1.x += beta*e1.x; v1.y += beta*e1.y;
            }
            *(float2*)(C + o0) = v0;
            *(float2*)(C + o1) = v1;
        }
    }
}

// ---------------- FP16 GEMM, fp16 output (alpha only) ----------------
__global__ __launch_bounds__(256, 2) void gemm_f16h(
    int Ni, int Ki, float alpha,
    const __half* __restrict__ A, const __half* __restrict__ Bw,
    __half* __restrict__ C)
{
    extern __shared__ uint32_t smp[];
    uint32_t* As[2] = { smp,          smp + 2*STGP };
    uint32_t* Bs[2] = { smp + STGP,   smp + 3*STGP };

    const int tid = threadIdx.x;
    const int bm = blockIdx.y * TBM, bn = blockIdx.x * TBN;
    const int warp = tid >> 5, lane = tid & 31;
    const int g = lane >> 2, t = lane & 3;
    const int wm = (warp >> 2) * 64;
    const int wn = (warp & 3) * 32;

    const int lrow = tid >> 3;
    const int lch  = tid & 7;

    const int nk = Ki / TBK;

    {
        #pragma unroll
        for (int q = 0; q < 4; ++q) {
            int row = lrow + q*32;
            cp_async16(smem_u32(As[0] + row*TSTP + lch*4),
                       A + (size_t)(bm + row)*Ki + lch*8, 16);
            int brow = bn + row;
            const __half* srcB = Bw + (size_t)(brow < Ni ? brow : 0)*Ki + lch*8;
            cp_async16(smem_u32(Bs[0] + row*TSTP + lch*4), srcB, brow < Ni ? 16 : 0);
        }
        CP_COMMIT();
    }

    float acc[4][4][4];
    #pragma unroll
    for (int i = 0; i < 4; ++i)
        #pragma unroll
        for (int j = 0; j < 4; ++j)
            #pragma unroll
            for (int r = 0; r < 4; ++r) acc[i][j][r] = 0.f;

    for (int j = 0; j < nk; ++j) {
        const int b = j & 1;
        if (j + 1 < nk) {
            const int k0 = (j + 1) * TBK;
            const int nb = b ^ 1;
            #pragma unroll
            for (int q = 0; q < 4; ++q) {
                int row = lrow + q*32;
                cp_async16(smem_u32(As[nb] + row*TSTP + lch*4),
                           A + (size_t)(bm + row)*Ki + k0 + lch*8, 16);
                int brow = bn + row;
                const __half* srcB = Bw + (size_t)(brow < Ni ? brow : 0)*Ki + k0 + lch*8;
                cp_async16(smem_u32(Bs[nb] + row*TSTP + lch*4), srcB, brow < Ni ? 16 : 0);
            }
        }
        CP_COMMIT();
        CP_WAIT1();
        __syncthreads();

        const uint32_t* as = As[b];
        const uint32_t* bs = Bs[b];
        #pragma unroll
        for (int ks = 0; ks < TBK/16; ++ks) {
            uint32_t af[4][4];
            #pragma unroll
            for (int i = 0; i < 4; ++i) {
                const uint32_t* r0 = as + (wm + i*16 + g)*TSTP + ks*8 + t;
                const uint32_t* r1 = r0 + 8*TSTP;
                af[i][0] = r0[0];
                af[i][1] = r1[0];
                af[i][2] = r0[4];
                af[i][3] = r1[4];
            }
            uint32_t bf[4][2];
            #pragma unroll
            for (int jj = 0; jj < 4; ++jj) {
                const uint32_t* base = bs + (wn + jj*8 + g)*TSTP + ks*8 + t;
                bf[jj][0] = base[0];
                bf[jj][1] = base[4];
            }
            #pragma unroll
            for (int i = 0; i < 4; ++i)
                #pragma unroll
                for (int jj = 0; jj < 4; ++jj)
                    mma_f16(acc[i][jj], af[i], bf[jj]);
        }
        __syncthreads();
    }

    #pragma unroll
    for (int i = 0; i < 4; ++i) {
        int row0 = bm + wm + i*16 + g;
        #pragma unroll
        for (int j = 0; j < 4; ++j) {
            int col = bn + wn + j*8 + 2*t;
            if (col >= Ni) continue;
            *(uint32_t*)(C + (size_t)row0 * Ni + col) =
                packh2(alpha*acc[i][j][0], alpha*acc[i][j][1]);
            *(uint32_t*)(C + (size_t)(row0 + 8) * Ni + col) =
                packh2(alpha*acc[i][j][2], alpha*acc[i][j][3]);
        }
    }
}

// ---------------- RMS norm: hs16 = f16(rms(x)*w) ----------------
__global__ __launch_bounds__(256) void rms_kernel(
    const float* __restrict__ x, const float* __restrict__ w, __half* __restrict__ out)
{
    int m = blockIdx.x;
    const float* xr = x + (size_t)m * HID;
    float v[8]; float ss = 0.f;
    #pragma unroll
    for (int k = 0; k < 8; ++k) { v[k] = xr[threadIdx.x + k*256]; ss += v[k]*v[k]; }
    ss = blockReduceSum256(ss);
    __shared__ float s_inv;
    if (threadIdx.x == 0) s_inv = rsqrtf(ss * (1.f/HID) + EPS_);
    __syncthreads();
    float inv = s_inv;
    __half* o = out + (size_t)m * HID;
    #pragma unroll
    for (int k = 0; k < 8; ++k) { int c = threadIdx.x + k*256; o[c] = __float2half_rn(v[k]*inv*w[c]); }
}

// ---------------- RoPE on fp16 qkv -> fp16 q (x1/8) and k (head-major) ----------
__global__ void rope_kernel(const __half* __restrict__ qkv, const int* __restrict__ positions,
                            __half* __restrict__ q16, __half* __restrict__ k16) {
    int idx = blockIdx.x*256 + threadIdx.x;
    const int total = MROWS*(NH+NKV)*32;
    if (idx >= total) return;
    int i = idx & 31; int rest = idx >> 5;
    int head = rest % (NH+NKV); int ml = rest / (NH+NKV);
    int l = ml % L_, b = ml / L_;
    float inv = powf(1e11f, -(float)i/32.0f);
    float ang = (float)positions[l] * inv;
    float c = cosf(ang), s = sinf(ang);
    if (head < NH) {
        const __half* p = qkv + (size_t)ml*QKV_DIM + head*HD;
        float x1 = __half2float(p[i]), x2 = __half2float(p[i+32]);
        __half* o = q16 + (size_t)ml*(NH*HD) + head*HD;
        o[i]    = __float2half_rn((x1*c - x2*s) * 0.125f);
        o[i+32] = __float2half_rn((x2*c + x1*s) * 0.125f);
    } else {
        int g = head - NH;
        const __half* p = qkv + (size_t)ml*QKV_DIM + NH*HD + g*HD;
        float x1 = __half2float(p[i])*KEY_MULT, x2 = __half2float(p[i+32])*KEY_MULT;
        __half* o = k16 + ((size_t)(b*NKV + g)*L_ + l)*HD;
        o[i]    = __float2half_rn(x1*c - x2*s);
        o[i+32] = __float2half_rn(x2*c + x1*s);
    }
}

// ---------------- V transpose: fp16 qkv v-part -> v16t [b][g][d][L] --------------
__global__ __launch_bounds__(256) void vtrans_kernel(
    const __half* __restrict__ qkv, __half* __restrict__ v16t)
{
    __shared__ __half ts[64][65];
    const int lt = blockIdx.x, g = blockIdx.y, b = blockIdx.z;
    const int vcol = NH*HD + NKV*HD + g*HD;
    const int tid = threadIdx.x;
    #pragma unroll
    for (int q = 0; q < 16; ++q) {
        int idx = tid + q*256;
        int row = idx >> 6, col = idx & 63;
        ts[col][row] = qkv[(size_t)(b*L_ + lt*64 + row)*QKV_DIM + vcol + col];
    }
    __syncthreads();
    #pragma unroll
    for (int q = 0; q < 16; ++q) {
        int idx = tid + q*256;
        int d = idx >> 6, l = idx & 63;
        v16t[((size_t)(b*NKV + g)*HD + d)*L_ + lt*64 + l] = ts[d][l];
    }
}

// ---------------- tensor-core flash attention (causal, GQA, HD=64) --------------
__global__ __launch_bounds__(128) void attn_kernel(
    const __half* __restrict__ q16, const __half* __restrict__ k16,
    const __half* __restrict__ v16t, __half* __restrict__ ctx)
{
    __shared__ uint32_t Qs[64*36];
    __shared__ uint32_t Ks[64*36];
    __shared__ uint32_t Vs[64*36];
    const int tid = threadIdx.x;
    const int warp = tid >> 5, lane = tid & 31;
    const int g = lane >> 2, t = lane & 3;
    const int wm = warp*16;
    const int qb = blockIdx.x, h = blockIdx.y, b = blockIdx.z;
    const int kg = h >> 2;

    {
        const __half* qp = q16 + (size_t)(b*L_ + qb*64)*(NH*HD) + h*HD;
        #pragma unroll
        for (int q = 0; q < 4; ++q) {
            int idx = tid + q*128;
            int row = idx >> 3, ch = idx & 7;
            *(uint4*)(&Qs[row*36 + ch*4]) =
                *(const uint4*)(qp + (size_t)row*(NH*HD) + ch*8);
        }
    }
    __syncthreads();

    uint32_t aq[4][4];
    #pragma unroll
    for (int ks = 0; ks < 4; ++ks) {
        const uint32_t* r0 = Qs + (wm + g)*36 + ks*8 + t;
        const uint32_t* r1 = Qs + (wm + g + 8)*36 + ks*8 + t;
        aq[ks][0] = r0[0]; aq[ks][1] = r1[0]; aq[ks][2] = r0[4]; aq[ks][3] = r1[4];
    }

    float oacc[8][4];
    #pragma unroll
    for (int jj = 0; jj < 8; ++jj)
        #pragma unroll
        for (int r = 0; r < 4; ++r) oacc[jj][r] = 0.f;
    float m_a = -1e30f, m_b = -1e30f, l_a = 0.f, l_b = 0.f;

    const __half* kp = k16 + (size_t)(b*NKV + kg)*L_*HD;
    const __half* vp = v16t + (size_t)(b*NKV + kg)*HD*L_;

    for (int j = 0; j <= qb; ++j) {
        __syncthreads();
        #pragma unroll
        for (int q = 0; q < 4; ++q) {
            int idx = tid + q*128;
            int row = idx >> 3, ch = idx & 7;
            *(uint4*)(&Ks[row*36 + ch*4]) =
                *(const uint4*)(kp + (size_t)(j*64 + row)*HD + ch*8);
            *(uint4*)(&Vs[row*36 + ch*4]) =
                *(const uint4*)(vp + (size_t)row*L_ + j*64 + ch*8);
        }
        __syncthreads();

        float sacc[8][4];
        #pragma unroll
        for (int jj = 0; jj < 8; ++jj)
            #pragma unroll
            for (int r = 0; r < 4; ++r) sacc[jj][r] = 0.f;
        #pragma unroll
        for (int ks = 0; ks < 4; ++ks) {
            #pragma unroll
            for (int jj = 0; jj < 8; ++jj) {
                uint32_t bk[2];
                const uint32_t* base = Ks + (jj*8 + g)*36 + ks*8 + t;
                bk[0] = base[0]; bk[1] = base[4];
                mma_f16(sacc[jj], aq[ks], bk);
            }
        }

        if (j == qb) {
            const int ra = wm + g, rb = ra + 8;
            #pragma unroll
            for (int jj = 0; jj < 8; ++jj) {
                int c0 = jj*8 + 2*t, c1 = c0 + 1;
                if (c0 > ra) sacc[jj][0] = -1e30f;
                if (c1 > ra) sacc[jj][1] = -1e30f;
                if (c0 > rb) sacc[jj][2] = -1e30f;
                if (c1 > rb) sacc[jj][3] = -1e30f;
            }
        }

        float mx_a = -1e30f, mx_b = -1e30f;
        #pragma unroll
        for (int jj = 0; jj < 8; ++jj) {
            mx_a = fmaxf(mx_a, fmaxf(sacc[jj][0], sacc[jj][1]));
            mx_b = fmaxf(mx_b, fmaxf(sacc[jj][2], sacc[jj][3]));
        }
        mx_a = fmaxf(mx_a, __shfl_xor_sync(0xffffffffu, mx_a, 1));
        mx_a = fmaxf(mx_a, __shfl_xor_sync(0xffffffffu, mx_a, 2));
        mx_b = fmaxf(mx_b, __shfl_xor_sync(0xffffffffu, mx_b, 1));
        mx_b = fmaxf(mx_b, __shfl_xor_sync(0xffffffffu, mx_b, 2));
        float mna = fmaxf(m_a, mx_a), mnb = fmaxf(m_b, mx_b);
        float ca = __expf(m_a - mna), cb = __expf(m_b - mnb);
        m_a = mna; m_b = mnb;
        float sa = 0.f, sb = 0.f;
        #pragma unroll
        for (int jj = 0; jj < 8; ++jj) {
            sacc[jj][0] = __expf(sacc[jj][0] - mna);
            sacc[jj][1] = __expf(sacc[jj][1] - mna);
            sacc[jj][2] = __expf(sacc[jj][2] - mnb);
            sacc[jj][3] = __expf(sacc[jj][3] - mnb);
            sa += sacc[jj][0] + sacc[jj][1];
            sb += sacc[jj][2] + sacc[jj][3];
        }
        sa += __shfl_xor_sync(0xffffffffu, sa, 1);
        sa += __shfl_xor_sync(0xffffffffu, sa, 2);
        sb += __shfl_xor_sync(0xffffffffu, sb, 1);
        sb += __shfl_xor_sync(0xffffffffu, sb, 2);
        l_a = l_a*ca + sa; l_b = l_b*cb + sb;
        #pragma unroll
        for (int jj = 0; jj < 8; ++jj) {
            oacc[jj][0] *= ca; oacc[jj][1] *= ca;
            oacc[jj][2] *= cb; oacc[jj][3] *= cb;
        }

        uint32_t aP[4][4];
        #pragma unroll
        for (int s = 0; s < 4; ++s) {
            aP[s][0] = packh2(sacc[2*s][0],   sacc[2*s][1]);
            aP[s][1] = packh2(sacc[2*s][2],   sacc[2*s][3]);
            aP[s][2] = packh2(sacc[2*s+1][0], sacc[2*s+1][1]);
            aP[s][3] = packh2(sacc[2*s+1][2], sacc[2*s+1][3]);
        }

        #pragma unroll
        for (int s = 0; s < 4; ++s) {
            #pragma unroll
            for (int jj = 0; jj < 8; ++jj) {
                uint32_t bv[2];
                const uint32_t* base = Vs + (jj*8 + g)*36 + s*8 + t;
                bv[0] = base[0]; bv[1] = base[4];
                mma_f16(oacc[jj], aP[s], bv);
            }
        }
    }

    float ila = 1.f / l_a, ilb = 1.f / l_b;
    int ra = qb*64 + wm + g;
    __half* op = ctx + (size_t)(b*L_ + ra)*HID + h*HD + 2*t;
    #pragma unroll
    for (int jj = 0; jj < 8; ++jj) {
        *(uint32_t*)(op + jj*8) = packh2(oacc[jj][0]*ila, oacc[jj][1]*ila);
        *(uint32_t*)(op + 8*HID + jj*8) = packh2(oacc[jj][2]*ilb, oacc[jj][3]*ilb);
    }
}

// ---------------- depthwise causal conv (MK=4) + mup + bias + SiLU ----------------
__global__ void conv_kernel(const float* __restrict__ proj, const float* __restrict__ cw,
                            const float* __restrict__ cb, float* __restrict__ out)
{
    int idx = blockIdx.x*256 + threadIdx.x;
    if (idx >= MROWS*CONV_DIM) return;
    int c = idx % CONV_DIM;
    int ml = idx / CONV_DIM;
    int l = ml % L_, b = ml / L_;
    float mupf = (c < DSSM) ? 0.9f : ((c < DSSM+MS) ? 0.8f : 1.1f);
    float s = 0.f;
    #pragma unroll
    for (int k = 0; k < MK; ++k) {
        int ls = l + k - (MK-1);
        if (ls >= 0) s += proj[(size_t)(b*L_+ls)*PROJ_DIM + DSSM + c] * cw[c*MK + k];
    }
    s = mupf*s + cb[c];
    out[idx] = siluf(s);
}

// ---------------- Mamba2 selective scan ----------------
#define SCT 32
__global__ __launch_bounds__(256) void scan_kernel(
    const float* __restrict__ conv, const float* __restrict__ proj,
    const float* __restrict__ A_log, const float* __restrict__ dt_bias,
    const float* __restrict__ Dp, float* __restrict__ y)
{
    const int b = blockIdx.x / MH, h = blockIdx.x % MH;
    const int tid = threadIdx.x;
    const int p = tid >> 2, sg = tid & 3, s0 = sg*16;
    const float Ah = -__expf(A_log[h]);
    const float Dh = Dp[h];
    const float dtb = dt_bias[h];
    float st[16];
    #pragma unroll
    for (int i = 0; i < 16; ++i) st[i] = 0.f;

    __shared__ float xs[SCT][64], Bsh[SCT][64], Csh[SCT][64], dts[SCT];

    for (int l0 = 0; l0 < L_; l0 += SCT) {
        __syncthreads();
        for (int i = tid; i < SCT*64; i += 256) {
            int t = i >> 6, c = i & 63;
            size_t base = (size_t)(b*L_ + l0 + t)*CONV_DIM;
            xs[t][c]  = conv[base + h*64 + c];
            Bsh[t][c] = conv[base + DSSM + c];
            Csh[t][c] = conv[base + DSSM + MS + c];
        }
        for (int i = tid; i < SCT; i += 256) {
            float r = proj[(size_t)(b*L_ + l0 + i)*PROJ_DIM + (PROJ_DIM-MH) + h] * 1.2f + dtb;
            dts[i] = (r > 20.f) ? r : log1pf(expf(r));   // softplus
        }
        __syncthreads();
        for (int t = 0; t < SCT; ++t) {
            float dt = dts[t];
            float dA = __expf(dt * Ah);
            float xv = xs[t][p];
            float coef = dt * xv;
            float acc = 0.f;
            #pragma unroll
            for (int ss = 0; ss < 16; ++ss) {
                st[ss] = st[ss]*dA + coef*Bsh[t][s0+ss];
                acc = fmaf(st[ss], Csh[t][s0+ss], acc);
            }
            acc += __shfl_xor_sync(0xffffffffu, acc, 1);
            acc += __shfl_xor_sync(0xffffffffu, acc, 2);
            if (sg == 0)
                y[(size_t)(b*L_ + l0 + t)*DSSM + h*64 + p] = acc + xv*Dh;
        }
    }
}

// ---------------- gating + RMS -> fp16 ----------------
__global__ __launch_bounds__(256) void gate_rms_kernel(
    const float* __restrict__ y, const float* __restrict__ proj,
    const float* __restrict__ w, __half* __restrict__ out)
{
    int m = blockIdx.x;
    const float* yr = y + (size_t)m*DSSM;
    const float* zr = proj + (size_t)m*PROJ_DIM;
    float v[8]; float ss = 0.f;
    #pragma unroll
    for (int k = 0; k < 8; ++k) {
        int c = threadIdx.x + k*256;
        float z = zr[c];
        float gv = yr[c] * siluf(z);
        v[k] = gv; ss += gv*gv;
    }
    ss = blockReduceSum256(ss);
    __shared__ float s_inv;
    if (threadIdx.x == 0) s_inv = rsqrtf(ss * (1.f/DSSM) + EPS_);
    __syncthreads();
    float inv = s_inv;
    __half* o = out + (size_t)m*DSSM;
    #pragma unroll
    for (int k = 0; k < 8; ++k) { int c = threadIdx.x + k*256; o[c] = __float2half_rn(v[k]*inv*w[c]); }
}

// ---------------- combine: h = as + residual ; hn16 = f16(rms(h)*w) ----------------
__global__ __launch_bounds__(256) void combine_kernel(
    const float* __restrict__ as_, const float* __restrict__ resid,
    const float* __restrict__ w, float* __restrict__ h, __half* __restrict__ hn)
{
    int m = blockIdx.x;
    const float* ar = as_  + (size_t)m*HID;
    const float* rr = resid + (size_t)m*HID;
    float v[8]; float ss = 0.f;
    #pragma unroll
    for (int k = 0; k < 8; ++k) {
        int c = threadIdx.x + k*256;
        float hv = ar[c] + rr[c];
        v[k] = hv; ss += hv*hv;
    }
    ss = blockReduceSum256(ss);
    __shared__ float s_inv;
    if (threadIdx.x == 0) s_inv = rsqrtf(ss * (1.f/HID) + EPS_);
    __syncthreads();
    float inv = s_inv;
    float* ho = h + (size_t)m*HID;
    __half* no = hn + (size_t)m*HID;
    #pragma unroll
    for (int k = 0; k < 8; ++k) {
        int c = threadIdx.x + k*256;
        ho[c] = v[k];
        no[c] = __float2half_rn(v[k]*inv*w[c]);
    }
}

// ---------------- SwiGLU activation on fp16 gu -> fp16 ----------------
__global__ void act_kernel(const __half* __restrict__ gu, __half* __restrict__ act) {
    int idx = blockIdx.x*256 + threadIdx.x;
    if (idx >= MROWS*INTER/2) return;
    int m = idx / (INTER/2);
    int i = (idx % (INTER/2)) * 2;
    const __half* row = gu + (size_t)m*(2*INTER);
    __half2 g2 = *(const __half2*)(row + i);
    __half2 u2 = *(const __half2*)(row + INTER + i);
    float g0 = __half2float(g2.x) * GATE_MULT;
    float g1 = __half2float(g2.y) * GATE_MULT;
    float a0 = siluf(g0) * __half2float(u2.x);
    float a1 = siluf(g1) * __half2float(u2.y);
    *(uint32_t*)(act + (size_t)m*INTER + i) = packh2(a0, a1);
}

// ---------------- host launcher (two-stream fork/join, graph-capture safe) -------
extern "C" void kernel_launch(void* const* d_in, const int* in_sizes, int n_in,
                              void* d_out, int out_size)
{
    const float* hidden      = (const float*)d_in[0];
    const int*   positions   = (const int*)  d_in[1];
    const float* w_in_ln     = (const float*)d_in[2];
    const float* qkv_w       = (const float*)d_in[3];
    const float* o_w         = (const float*)d_in[4];
    const float* in_proj_w   = (const float*)d_in[5];
    const float* conv_w      = (const float*)d_in[6];
    const float* conv_b      = (const float*)d_in[7];
    const float* A_log       = (const float*)d_in[8];
    const float* dt_bias     = (const float*)d_in[9];
    const float* Dp          = (const float*)d_in[10];
    const float* ssm_norm_w  = (const float*)d_in[11];
    const float* out_proj_w  = (const float*)d_in[12];
    const float* w_pre_ff_ln = (const float*)d_in[13];
    const float* gate_up_w   = (const float*)d_in[14];
    const float* down_w      = (const float*)d_in[15];
    float* out = (float*)d_out;

    float *proj, *conv, *y, *as_, *h;
    __half *qkv16, *gu16, *hs16, *ctx16, *gt16, *hn16, *act16, *w16, *q16, *k16, *v16t;
    cudaGetSymbolAddress((void**)&proj, g_proj);
    cudaGetSymbolAddress((void**)&conv, g_conv);
    cudaGetSymbolAddress((void**)&y,    g_y);
    cudaGetSymbolAddress((void**)&as_,  g_as);
    cudaGetSymbolAddress((void**)&h,    g_h);
    cudaGetSymbolAddress((void**)&qkv16,g_qkv16);
    cudaGetSymbolAddress((void**)&gu16, g_gu16);
    cudaGetSymbolAddress((void**)&hs16, g_hs16);
    cudaGetSymbolAddress((void**)&ctx16,g_ctx16);
    cudaGetSymbolAddress((void**)&gt16, g_gt16);
    cudaGetSymbolAddress((void**)&hn16, g_hn16);
    cudaGetSymbolAddress((void**)&act16,g_act16);
    cudaGetSymbolAddress((void**)&w16,  g_w16);
    cudaGetSymbolAddress((void**)&q16,  g_q16);
    cudaGetSymbolAddress((void**)&k16,  g_k16);
    cudaGetSymbolAddress((void**)&v16t, g_v16t);

    cudaFuncSetAttribute(gemm_f16,  cudaFuncAttributeMaxDynamicSharedMemorySize, GSMEM_BYTES);
    cudaFuncSetAttribute(gemm_f16h, cudaFuncAttributeMaxDynamicSharedMemorySize, GSMEM_BYTES);

    // side stream + events, created once (same captured work on every call)
    static cudaStream_t s2 = nullptr;
    static cudaEvent_t ev_fork, ev_cvt, ev_proj, ev_mamba;
    if (!s2) {
        cudaStreamCreateWithFlags(&s2, cudaStreamNonBlocking);
        cudaEventCreateWithFlags(&ev_fork,  cudaEventDisableTiming);
        cudaEventCreateWithFlags(&ev_cvt,   cudaEventDisableTiming);
        cudaEventCreateWithFlags(&ev_proj,  cudaEventDisableTiming);
        cudaEventCreateWithFlags(&ev_mamba, cudaEventDisableTiming);
    }

    const int MT = MROWS/TBM;   // 16

    #define CVT_S(src, dstoff, n, strm) \
        cvt_f16_kernel<<<((n)/4 + 255)/256, 256, 0, strm>>>(src, w16 + (size_t)(dstoff), (n)/4)

    // ---- fork: side stream converts the non-critical weights ----
    cudaEventRecord(ev_fork, 0);
    cudaStreamWaitEvent(s2, ev_fork, 0);
    CVT_S(o_w,        W16_O,       HID*HID,       s2);
    CVT_S(out_proj_w, W16_OUTPROJ, HID*DSSM,      s2);
    CVT_S(gate_up_w,  W16_GATEUP,  2*INTER*HID,   s2);
    CVT_S(down_w,     W16_DOWN,    HID*INTER,     s2);
    cudaEventRecord(ev_cvt, s2);

    // ---- main stream: critical path ----
    CVT_S(qkv_w,     W16_QKV,    QKV_DIM*HID,  0);
    CVT_S(in_proj_w, W16_INPROJ, PROJ_DIM*HID, 0);
    rms_kernel<<<MROWS, 256>>>(hidden, w_in_ln, hs16);

    gemm_f16h<<<dim3(QKV_DIM/TBN, MT), 256, GSMEM_BYTES>>>(QKV_DIM, HID, ATTN_IN,
                                            hs16, w16 + W16_QKV, qkv16);
    gemm_f16<<<dim3((PROJ_DIM+TBN-1)/TBN, MT), 256, GSMEM_BYTES>>>(PROJ_DIM, HID, SSM_IN,
                                            hs16, w16 + W16_INPROJ, 0.f, nullptr, proj);
    cudaEventRecord(ev_proj, 0);

    // ---- side stream: mamba chain (needs proj + its cvts) ----
    cudaStreamWaitEvent(s2, ev_proj, 0);
    conv_kernel<<<(MROWS*CONV_DIM + 255)/256, 256, 0, s2>>>(proj, conv_w, conv_b, conv);
    scan_kernel<<<B_*MH, 256, 0, s2>>>(conv, proj, A_log, dt_bias, Dp, y);
    gate_rms_kernel<<<MROWS, 256, 0, s2>>>(y, proj, ssm_norm_w, gt16);
    cudaEventRecord(ev_mamba, s2);

    // ---- main stream: attention branch ----
    rope_kernel<<<(MROWS*(NH+NKV)*32 + 255)/256, 256>>>(qkv16, positions, q16, k16);
    vtrans_kernel<<<dim3(L_/64, NKV, B_), 256>>>(qkv16, v16t);
    attn_kernel<<<dim3(L_/64, NH, B_), 128>>>(q16, k16, v16t, ctx16);

    cudaStreamWaitEvent(0, ev_cvt, 0);       // o_w (and later weights) ready
    gemm_f16<<<dim3(HID/TBN, MT), 256, GSMEM_BYTES>>>(HID, HID, ATTN_OUT,
                                            ctx16, w16 + W16_O, 0.f, nullptr, as_);

    cudaStreamWaitEvent(0, ev_mamba, 0);     // gt16 ready; join side stream
    gemm_f16<<<dim3(HID/TBN, MT), 256, GSMEM_BYTES>>>(HID, DSSM, SSM_OUT,
                                            gt16, w16 + W16_OUTPROJ, 1.f, as_, as_);

    combine_kernel<<<MROWS, 256>>>(as_, hidden, w_pre_ff_ln, h, hn16);

    gemm_f16h<<<dim3(2*INTER/TBN, MT), 256, GSMEM_BYTES>>>(2*INTER, HID, 1.f,
                                            hn16, w16 + W16_GATEUP, gu16);
    act_kernel<<<(MROWS*INTER/2 + 255)/256, 256>>>(gu16, act16);
    gemm_f16<<<dim3(HID/TBN, MT), 256, GSMEM_BYTES>>>(HID, INTER, DOWN_MULT,
                                            act16, w16 + W16_DOWN, 1.f, h, out);
    #undef CVT_S
    (void)in_sizes; (void)n_in; (void)out_size;
}

// round 15
// speedup vs baseline: 1.3089x; 1.0169x over previous
#include <cuda_runtime.h>
#include <cuda_fp16.h>
#include <math.h>
#include <stdint.h>

#define B_ 2
#define L_ 1024
#define HID 2048
#define NH 32
#define HD 64
#define NKV 8
#define INTER 8192
#define DSSM 2048
#define MH 32
#define MP 64
#define MS 64
#define MK 4
#define CONV_DIM (DSSM + 2*MS)          // 2176
#define PROJ_DIM (2*DSSM + 2*MS + MH)   // 4256
#define QKV_DIM (NH*HD + 2*NKV*HD)      // 3072
#define MROWS (B_*L_)                   // 2048

#define ATTN_IN 1.2f
#define ATTN_OUT 0.8f
#define KEY_MULT 0.7f
#define SSM_IN 1.1f
#define SSM_OUT 0.9f
#define GATE_MULT 0.9f
#define DOWN_MULT 0.8f
#define EPS_ 1e-5f

// ---------------- scratch (device globals; no allocation allowed) ----------------
__device__ float  g_proj[MROWS*PROJ_DIM];
__device__ float  g_conv[MROWS*CONV_DIM];
__device__ float  g_y   [MROWS*DSSM];
__device__ float  g_as  [MROWS*HID];
__device__ float  g_h   [MROWS*HID];

__device__ __half g_qkv16[MROWS*QKV_DIM];
__device__ __half g_gu16 [(size_t)MROWS*2*INTER];
__device__ __half g_hs16 [MROWS*HID];
__device__ __half g_ctx16[MROWS*HID];
__device__ __half g_gt16 [MROWS*DSSM];
__device__ __half g_hn16 [MROWS*HID];
__device__ __half g_act16[(size_t)MROWS*INTER];
__device__ __half g_q16  [MROWS*NH*HD];
__device__ __half g_k16  [B_*NKV*L_*HD];
__device__ __half g_v16t [B_*NKV*HD*L_];

// fp16 weights, one big buffer
#define W16_QKV     0
#define W16_INPROJ  (W16_QKV    + QKV_DIM*HID)
#define W16_O       (W16_INPROJ + PROJ_DIM*HID)
#define W16_OUTPROJ (W16_O      + HID*HID)
#define W16_GATEUP  (W16_OUTPROJ+ HID*DSSM)
#define W16_DOWN    (W16_GATEUP + 2*INTER*HID)
#define W16_TOTAL   (W16_DOWN   + HID*INTER)
__device__ __half g_w16[W16_TOTAL];

// ---------------- helpers ----------------
__device__ __forceinline__ float blockReduceSum256(float v) {
    __shared__ float sh[8];
    int lane = threadIdx.x & 31, w = threadIdx.x >> 5;
    #pragma unroll
    for (int o = 16; o; o >>= 1) v += __shfl_xor_sync(0xffffffffu, v, o);
    if (lane == 0) sh[w] = v;
    __syncthreads();
    v = (threadIdx.x < 8) ? sh[threadIdx.x] : 0.f;
    if (w == 0) {
        #pragma unroll
        for (int o = 4; o; o >>= 1) v += __shfl_xor_sync(0xffu, v, o);
    }
    return v;
}

__device__ __forceinline__ float siluf(float x) { return x / (1.f + __expf(-x)); }

__device__ __forceinline__ void mma_f16(float* c, const uint32_t* a, const uint32_t* b) {
    asm volatile(
        "mma.sync.aligned.m16n8k16.row.col.f32.f16.f16.f32 "
        "{%0,%1,%2,%3}, {%4,%5,%6,%7}, {%8,%9}, {%0,%1,%2,%3};"
        : "+f"(c[0]), "+f"(c[1]), "+f"(c[2]), "+f"(c[3])
        : "r"(a[0]), "r"(a[1]), "r"(a[2]), "r"(a[3]), "r"(b[0]), "r"(b[1]));
}

__device__ __forceinline__ uint32_t smem_u32(const void* p) {
    uint32_t a;
    asm("{ .reg .u64 t; cvta.to.shared.u64 t, %1; cvt.u32.u64 %0, t; }" : "=r"(a) : "l"(p));
    return a;
}
__device__ __forceinline__ void cp_async16(uint32_t dst, const void* src, int srcBytes) {
    asm volatile("cp.async.cg.shared.global [%0], [%1], 16, %2;"
                 :: "r"(dst), "l"(src), "r"(srcBytes));
}
#define CP_COMMIT() asm volatile("cp.async.commit_group;" ::: "memory")
#define CP_WAIT1()  asm volatile("cp.async.wait_group 1;"  ::: "memory")

__device__ __forceinline__ uint32_t packh2(float a, float b) {
    __half2 h = __floats2half2_rn(a, b);
    return *(uint32_t*)&h;
}

// ---------------- fp32 -> fp16 weight convert (coalesced, 1 float4/thread) -------
__global__ void cvt_f16_kernel(const float* __restrict__ in, __half* __restrict__ out, int n4) {
    int i = blockIdx.x*256 + threadIdx.x;
    if (i >= n4) return;
    float4 v = *(const float4*)(in + (size_t)i*4);
    *(uint2*)(out + (size_t)i*4) = make_uint2(packh2(v.x, v.y), packh2(v.z, v.w));
}

// ---------------- FP16 tensor-core GEMM (fp32 out, alpha/beta) ----------------
#define TBM 128
#define TBN 128
#define TBK 64
#define TSTP 36
#define STGP (128*TSTP)
#define GSMEM_BYTES (4*STGP*4)           // 73728 B

__global__ __launch_bounds__(256, 2) void gemm_f16(
    int Ni, int Ki, float alpha,
    const __half* __restrict__ A, const __half* __restrict__ Bw,
    float beta, const float* __restrict__ Cin, float* __restrict__ C)
{
    extern __shared__ uint32_t smp[];
    uint32_t* As[2] = { smp,          smp + 2*STGP };
    uint32_t* Bs[2] = { smp + STGP,   smp + 3*STGP };

    const int tid = threadIdx.x;
    const int bm = blockIdx.y * TBM, bn = blockIdx.x * TBN;
    const int warp = tid >> 5, lane = tid & 31;
    const int g = lane >> 2, t = lane & 3;
    const int wm = (warp >> 2) * 64;
    const int wn = (warp & 3) * 32;

    const int lrow = tid >> 3;
    const int lch  = tid & 7;

    const int nk = Ki / TBK;

    {
        #pragma unroll
        for (int q = 0; q < 4; ++q) {
            int row = lrow + q*32;
            cp_async16(smem_u32(As[0] + row*TSTP + lch*4),
                       A + (size_t)(bm + row)*Ki + lch*8, 16);
            int brow = bn + row;
            const __half* srcB = Bw + (size_t)(brow < Ni ? brow : 0)*Ki + lch*8;
            cp_async16(smem_u32(Bs[0] + row*TSTP + lch*4), srcB, brow < Ni ? 16 : 0);
        }
        CP_COMMIT();
    }

    float acc[4][4][4];
    #pragma unroll
    for (int i = 0; i < 4; ++i)
        #pragma unroll
        for (int j = 0; j < 4; ++j)
            #pragma unroll
            for (int r = 0; r < 4; ++r) acc[i][j][r] = 0.f;

    for (int j = 0; j < nk; ++j) {
        const int b = j & 1;
        if (j + 1 < nk) {
            const int k0 = (j + 1) * TBK;
            const int nb = b ^ 1;
            #pragma unroll
            for (int q = 0; q < 4; ++q) {
                int row = lrow + q*32;
                cp_async16(smem_u32(As[nb] + row*TSTP + lch*4),
                           A + (size_t)(bm + row)*Ki + k0 + lch*8, 16);
                int brow = bn + row;
                const __half* srcB = Bw + (size_t)(brow < Ni ? brow : 0)*Ki + k0 + lch*8;
                cp_async16(smem_u32(Bs[nb] + row*TSTP + lch*4), srcB, brow < Ni ? 16 : 0);
            }
        }
        CP_COMMIT();
        CP_WAIT1();
        __syncthreads();

        const uint32_t* as = As[b];
        const uint32_t* bs = Bs[b];
        #pragma unroll
        for (int ks = 0; ks < TBK/16; ++ks) {
            uint32_t af[4][4];
            #pragma unroll
            for (int i = 0; i < 4; ++i) {
                const uint32_t* r0 = as + (wm + i*16 + g)*TSTP + ks*8 + t;
                const uint32_t* r1 = r0 + 8*TSTP;
                af[i][0] = r0[0];
                af[i][1] = r1[0];
                af[i][2] = r0[4];
                af[i][3] = r1[4];
            }
            uint32_t bf[4][2];
            #pragma unroll
            for (int jj = 0; jj < 4; ++jj) {
                const uint32_t* base = bs + (wn + jj*8 + g)*TSTP + ks*8 + t;
                bf[jj][0] = base[0];
                bf[jj][1] = base[4];
            }
            #pragma unroll
            for (int i = 0; i < 4; ++i)
                #pragma unroll
                for (int jj = 0; jj < 4; ++jj)
                    mma_f16(acc[i][jj], af[i], bf[jj]);
        }
        __syncthreads();
    }

    #pragma unroll
    for (int i = 0; i < 4; ++i) {
        int row0 = bm + wm + i*16 + g;
        #pragma unroll
        for (int j = 0; j < 4; ++j) {
            int col = bn + wn + j*8 + 2*t;
            if (col >= Ni) continue;
            size_t o0 = (size_t)row0 * Ni + col;
            size_t o1 = (size_t)(row0 + 8) * Ni + col;
            float2 v0 = make_float2(alpha*acc[i][j][0], alpha*acc[i][j][1]);
            float2 v1 = make_float2(alpha*acc[i][j][2], alpha*acc[i][j][3]);
            if (beta != 0.f) {
                float2 e0 = *(const float2*)(Cin + o0);
                float2 e1 = *(const float2*)(Cin + o1);
                v0.x += beta*e0.x; v0.y += beta*e0.y;
                v1.x += beta*e1.x; v1.y += beta*e1.y;
            }
            *(float2*)(C + o0) = v0;
            *(float2*)(C + o1) = v1;
        }
    }
}

// ---------------- FP16 GEMM, fp16 output (alpha only) ----------------
__global__ __launch_bounds__(256, 2) void gemm_f16h(
    int Ni, int Ki, float alpha,
    const __half* __restrict__ A, const __half* __restrict__ Bw,
    __half* __restrict__ C)
{
    extern __shared__ uint32_t smp[];
    uint32_t* As[2] = { smp,          smp + 2*STGP };
    uint32_t* Bs[2] = { smp + STGP,   smp + 3*STGP };

    const int tid = threadIdx.x;
    const int bm = blockIdx.y * TBM, bn = blockIdx.x * TBN;
    const int warp = tid >> 5, lane = tid & 31;
    const int g = lane >> 2, t = lane & 3;
    const int wm = (warp >> 2) * 64;
    const int wn = (warp & 3) * 32;

    const int lrow = tid >> 3;
    const int lch  = tid & 7;

    const int nk = Ki / TBK;

    {
        #pragma unroll
        for (int q = 0; q < 4; ++q) {
            int row = lrow + q*32;
            cp_async16(smem_u32(As[0] + row*TSTP + lch*4),
                       A + (size_t)(bm + row)*Ki + lch*8, 16);
            int brow = bn + row;
            const __half* srcB = Bw + (size_t)(brow < Ni ? brow : 0)*Ki + lch*8;
            cp_async16(smem_u32(Bs[0] + row*TSTP + lch*4), srcB, brow < Ni ? 16 : 0);
        }
        CP_COMMIT();
    }

    float acc[4][4][4];
    #pragma unroll
    for (int i = 0; i < 4; ++i)
        #pragma unroll
        for (int j = 0; j < 4; ++j)
            #pragma unroll
            for (int r = 0; r < 4; ++r) acc[i][j][r] = 0.f;

    for (int j = 0; j < nk; ++j) {
        const int b = j & 1;
        if (j + 1 < nk) {
            const int k0 = (j + 1) * TBK;
            const int nb = b ^ 1;
            #pragma unroll
            for (int q = 0; q < 4; ++q) {
                int row = lrow + q*32;
                cp_async16(smem_u32(As[nb] + row*TSTP + lch*4),
                           A + (size_t)(bm + row)*Ki + k0 + lch*8, 16);
                int brow = bn + row;
                const __half* srcB = Bw + (size_t)(brow < Ni ? brow : 0)*Ki + k0 + lch*8;
                cp_async16(smem_u32(Bs[nb] + row*TSTP + lch*4), srcB, brow < Ni ? 16 : 0);
            }
        }
        CP_COMMIT();
        CP_WAIT1();
        __syncthreads();

        const uint32_t* as = As[b];
        const uint32_t* bs = Bs[b];
        #pragma unroll
        for (int ks = 0; ks < TBK/16; ++ks) {
            uint32_t af[4][4];
            #pragma unroll
            for (int i = 0; i < 4; ++i) {
                const uint32_t* r0 = as + (wm + i*16 + g)*TSTP + ks*8 + t;
                const uint32_t* r1 = r0 + 8*TSTP;
                af[i][0] = r0[0];
                af[i][1] = r1[0];
                af[i][2] = r0[4];
                af[i][3] = r1[4];
            }
            uint32_t bf[4][2];
            #pragma unroll
            for (int jj = 0; jj < 4; ++jj) {
                const uint32_t* base = bs + (wn + jj*8 + g)*TSTP + ks*8 + t;
                bf[jj][0] = base[0];
                bf[jj][1] = base[4];
            }
            #pragma unroll
            for (int i = 0; i < 4; ++i)
                #pragma unroll
                for (int jj = 0; jj < 4; ++jj)
                    mma_f16(acc[i][jj], af[i], bf[jj]);
        }
        __syncthreads();
    }

    #pragma unroll
    for (int i = 0; i < 4; ++i) {
        int row0 = bm + wm + i*16 + g;
        #pragma unroll
        for (int j = 0; j < 4; ++j) {
            int col = bn + wn + j*8 + 2*t;
            if (col >= Ni) continue;
            *(uint32_t*)(C + (size_t)row0 * Ni + col) =
                packh2(alpha*acc[i][j][0], alpha*acc[i][j][1]);
            *(uint32_t*)(C + (size_t)(row0 + 8) * Ni + col) =
                packh2(alpha*acc[i][j][2], alpha*acc[i][j][3]);
        }
    }
}

// ---------------- RMS norm: hs16 = f16(rms(x)*w) ----------------
__global__ __launch_bounds__(256) void rms_kernel(
    const float* __restrict__ x, const float* __restrict__ w, __half* __restrict__ out)
{
    int m = blockIdx.x;
    const float* xr = x + (size_t)m * HID;
    float v[8]; float ss = 0.f;
    #pragma unroll
    for (int k = 0; k < 8; ++k) { v[k] = xr[threadIdx.x + k*256]; ss += v[k]*v[k]; }
    ss = blockReduceSum256(ss);
    __shared__ float s_inv;
    if (threadIdx.x == 0) s_inv = rsqrtf(ss * (1.f/HID) + EPS_);
    __syncthreads();
    float inv = s_inv;
    __half* o = out + (size_t)m * HID;
    #pragma unroll
    for (int k = 0; k < 8; ++k) { int c = threadIdx.x + k*256; o[c] = __float2half_rn(v[k]*inv*w[c]); }
}

// ---------------- RoPE on fp16 qkv -> fp16 q (x1/8) and k (head-major) ----------
__global__ void rope_kernel(const __half* __restrict__ qkv, const int* __restrict__ positions,
                            __half* __restrict__ q16, __half* __restrict__ k16) {
    int idx = blockIdx.x*256 + threadIdx.x;
    const int total = MROWS*(NH+NKV)*32;
    if (idx >= total) return;
    int i = idx & 31; int rest = idx >> 5;
    int head = rest % (NH+NKV); int ml = rest / (NH+NKV);
    int l = ml % L_, b = ml / L_;
    float inv = powf(1e11f, -(float)i/32.0f);
    float ang = (float)positions[l] * inv;
    float c = cosf(ang), s = sinf(ang);
    if (head < NH) {
        const __half* p = qkv + (size_t)ml*QKV_DIM + head*HD;
        float x1 = __half2float(p[i]), x2 = __half2float(p[i+32]);
        __half* o = q16 + (size_t)ml*(NH*HD) + head*HD;
        o[i]    = __float2half_rn((x1*c - x2*s) * 0.125f);
        o[i+32] = __float2half_rn((x2*c + x1*s) * 0.125f);
    } else {
        int g = head - NH;
        const __half* p = qkv + (size_t)ml*QKV_DIM + NH*HD + g*HD;
        float x1 = __half2float(p[i])*KEY_MULT, x2 = __half2float(p[i+32])*KEY_MULT;
        __half* o = k16 + ((size_t)(b*NKV + g)*L_ + l)*HD;
        o[i]    = __float2half_rn(x1*c - x2*s);
        o[i+32] = __float2half_rn(x2*c + x1*s);
    }
}

// ---------------- V transpose: fp16 qkv v-part -> v16t [b][g][d][L] --------------
__global__ __launch_bounds__(256) void vtrans_kernel(
    const __half* __restrict__ qkv, __half* __restrict__ v16t)
{
    __shared__ __half ts[64][65];
    const int lt = blockIdx.x, g = blockIdx.y, b = blockIdx.z;
    const int vcol = NH*HD + NKV*HD + g*HD;
    const int tid = threadIdx.x;
    #pragma unroll
    for (int q = 0; q < 16; ++q) {
        int idx = tid + q*256;
        int row = idx >> 6, col = idx & 63;
        ts[col][row] = qkv[(size_t)(b*L_ + lt*64 + row)*QKV_DIM + vcol + col];
    }
    __syncthreads();
    #pragma unroll
    for (int q = 0; q < 16; ++q) {
        int idx = tid + q*256;
        int d = idx >> 6, l = idx & 63;
        v16t[((size_t)(b*NKV + g)*HD + d)*L_ + lt*64 + l] = ts[d][l];
    }
}

// ---------------- tensor-core flash attention (causal, GQA, HD=64) --------------
__global__ __launch_bounds__(128) void attn_kernel(
    const __half* __restrict__ q16, const __half* __restrict__ k16,
    const __half* __restrict__ v16t, __half* __restrict__ ctx)
{
    __shared__ uint32_t Qs[64*36];
    __shared__ uint32_t Ks[64*36];
    __shared__ uint32_t Vs[64*36];
    const int tid = threadIdx.x;
    const int warp = tid >> 5, lane = tid & 31;
    const int g = lane >> 2, t = lane & 3;
    const int wm = warp*16;
    const int qb = blockIdx.x, h = blockIdx.y, b = blockIdx.z;
    const int kg = h >> 2;

    {
        const __half* qp = q16 + (size_t)(b*L_ + qb*64)*(NH*HD) + h*HD;
        #pragma unroll
        for (int q = 0; q < 4; ++q) {
            int idx = tid + q*128;
            int row = idx >> 3, ch = idx & 7;
            *(uint4*)(&Qs[row*36 + ch*4]) =
                *(const uint4*)(qp + (size_t)row*(NH*HD) + ch*8);
        }
    }
    __syncthreads();

    uint32_t aq[4][4];
    #pragma unroll
    for (int ks = 0; ks < 4; ++ks) {
        const uint32_t* r0 = Qs + (wm + g)*36 + ks*8 + t;
        const uint32_t* r1 = Qs + (wm + g + 8)*36 + ks*8 + t;
        aq[ks][0] = r0[0]; aq[ks][1] = r1[0]; aq[ks][2] = r0[4]; aq[ks][3] = r1[4];
    }

    float oacc[8][4];
    #pragma unroll
    for (int jj = 0; jj < 8; ++jj)
        #pragma unroll
        for (int r = 0; r < 4; ++r) oacc[jj][r] = 0.f;
    float m_a = -1e30f, m_b = -1e30f, l_a = 0.f, l_b = 0.f;

    const __half* kp = k16 + (size_t)(b*NKV + kg)*L_*HD;
    const __half* vp = v16t + (size_t)(b*NKV + kg)*HD*L_;

    for (int j = 0; j <= qb; ++j) {
        __syncthreads();
        #pragma unroll
        for (int q = 0; q < 4; ++q) {
            int idx = tid + q*128;
            int row = idx >> 3, ch = idx & 7;
            *(uint4*)(&Ks[row*36 + ch*4]) =
                *(const uint4*)(kp + (size_t)(j*64 + row)*HD + ch*8);
            *(uint4*)(&Vs[row*36 + ch*4]) =
                *(const uint4*)(vp + (size_t)row*L_ + j*64 + ch*8);
        }
        __syncthreads();

        float sacc[8][4];
        #pragma unroll
        for (int jj = 0; jj < 8; ++jj)
            #pragma unroll
            for (int r = 0; r < 4; ++r) sacc[jj][r] = 0.f;
        #pragma unroll
        for (int ks = 0; ks < 4; ++ks) {
            #pragma unroll
            for (int jj = 0; jj < 8; ++jj) {
                uint32_t bk[2];
                const uint32_t* base = Ks + (jj*8 + g)*36 + ks*8 + t;
                bk[0] = base[0]; bk[1] = base[4];
                mma_f16(sacc[jj], aq[ks], bk);
            }
        }

        if (j == qb) {
            const int ra = wm + g, rb = ra + 8;
            #pragma unroll
            for (int jj = 0; jj < 8; ++jj) {
                int c0 = jj*8 + 2*t, c1 = c0 + 1;
                if (c0 > ra) sacc[jj][0] = -1e30f;
                if (c1 > ra) sacc[jj][1] = -1e30f;
                if (c0 > rb) sacc[jj][2] = -1e30f;
                if (c1 > rb) sacc[jj][3] = -1e30f;
            }
        }

        float mx_a = -1e30f, mx_b = -1e30f;
        #pragma unroll
        for (int jj = 0; jj < 8; ++jj) {
            mx_a = fmaxf(mx_a, fmaxf(sacc[jj][0], sacc[jj][1]));
            mx_b = fmaxf(mx_b, fmaxf(sacc[jj][2], sacc[jj][3]));
        }
        mx_a = fmaxf(mx_a, __shfl_xor_sync(0xffffffffu, mx_a, 1));
        mx_a = fmaxf(mx_a, __shfl_xor_sync(0xffffffffu, mx_a, 2));
        mx_b = fmaxf(mx_b, __shfl_xor_sync(0xffffffffu, mx_b, 1));
        mx_b = fmaxf(mx_b, __shfl_xor_sync(0xffffffffu, mx_b, 2));
        float mna = fmaxf(m_a, mx_a), mnb = fmaxf(m_b, mx_b);
        float ca = __expf(m_a - mna), cb = __expf(m_b - mnb);
        m_a = mna; m_b = mnb;
        float sa = 0.f, sb = 0.f;
        #pragma unroll
        for (int jj = 0; jj < 8; ++jj) {
            sacc[jj][0] = __expf(sacc[jj][0] - mna);
            sacc[jj][1] = __expf(sacc[jj][1] - mna);
            sacc[jj][2] = __expf(sacc[jj][2] - mnb);
            sacc[jj][3] = __expf(sacc[jj][3] - mnb);
            sa += sacc[jj][0] + sacc[jj][1];
            sb += sacc[jj][2] + sacc[jj][3];
        }
        sa += __shfl_xor_sync(0xffffffffu, sa, 1);
        sa += __shfl_xor_sync(0xffffffffu, sa, 2);
        sb += __shfl_xor_sync(0xffffffffu, sb, 1);
        sb += __shfl_xor_sync(0xffffffffu, sb, 2);
        l_a = l_a*ca + sa; l_b = l_b*cb + sb;
        #pragma unroll
        for (int jj = 0; jj < 8; ++jj) {
            oacc[jj][0] *= ca; oacc[jj][1] *= ca;
            oacc[jj][2] *= cb; oacc[jj][3] *= cb;
        }

        uint32_t aP[4][4];
        #pragma unroll
        for (int s = 0; s < 4; ++s) {
            aP[s][0] = packh2(sacc[2*s][0],   sacc[2*s][1]);
            aP[s][1] = packh2(sacc[2*s][2],   sacc[2*s][3]);
            aP[s][2] = packh2(sacc[2*s+1][0], sacc[2*s+1][1]);
            aP[s][3] = packh2(sacc[2*s+1][2], sacc[2*s+1][3]);
        }

        #pragma unroll
        for (int s = 0; s < 4; ++s) {
            #pragma unroll
            for (int jj = 0; jj < 8; ++jj) {
                uint32_t bv[2];
                const uint32_t* base = Vs + (jj*8 + g)*36 + s*8 + t;
                bv[0] = base[0]; bv[1] = base[4];
                mma_f16(oacc[jj], aP[s], bv);
            }
        }
    }

    float ila = 1.f / l_a, ilb = 1.f / l_b;
    int ra = qb*64 + wm + g;
    __half* op = ctx + (size_t)(b*L_ + ra)*HID + h*HD + 2*t;
    #pragma unroll
    for (int jj = 0; jj < 8; ++jj) {
        *(uint32_t*)(op + jj*8) = packh2(oacc[jj][0]*ila, oacc[jj][1]*ila);
        *(uint32_t*)(op + 8*HID + jj*8) = packh2(oacc[jj][2]*ilb, oacc[jj][3]*ilb);
    }
}

// ---------------- depthwise causal conv (MK=4) + mup + bias + SiLU ----------------
__global__ void conv_kernel(const float* __restrict__ proj, const float* __restrict__ cw,
                            const float* __restrict__ cb, float* __restrict__ out)
{
    int idx = blockIdx.x*256 + threadIdx.x;
    if (idx >= MROWS*CONV_DIM) return;
    int c = idx % CONV_DIM;
    int ml = idx / CONV_DIM;
    int l = ml % L_, b = ml / L_;
    float mupf = (c < DSSM) ? 0.9f : ((c < DSSM+MS) ? 0.8f : 1.1f);
    float s = 0.f;
    #pragma unroll
    for (int k = 0; k < MK; ++k) {
        int ls = l + k - (MK-1);
        if (ls >= 0) s += proj[(size_t)(b*L_+ls)*PROJ_DIM + DSSM + c] * cw[c*MK + k];
    }
    s = mupf*s + cb[c];
    out[idx] = siluf(s);
}

// ---------------- Mamba2 selective scan ----------------
#define SCT 32
__global__ __launch_bounds__(256) void scan_kernel(
    const float* __restrict__ conv, const float* __restrict__ proj,
    const float* __restrict__ A_log, const float* __restrict__ dt_bias,
    const float* __restrict__ Dp, float* __restrict__ y)
{
    const int b = blockIdx.x / MH, h = blockIdx.x % MH;
    const int tid = threadIdx.x;
    const int p = tid >> 2, sg = tid & 3, s0 = sg*16;
    const float Ah = -__expf(A_log[h]);
    const float Dh = Dp[h];
    const float dtb = dt_bias[h];
    float st[16];
    #pragma unroll
    for (int i = 0; i < 16; ++i) st[i] = 0.f;

    __shared__ float xs[SCT][64], Bsh[SCT][64], Csh[SCT][64], dts[SCT];

    for (int l0 = 0; l0 < L_; l0 += SCT) {
        __syncthreads();
        for (int i = tid; i < SCT*64; i += 256) {
            int t = i >> 6, c = i & 63;
            size_t base = (size_t)(b*L_ + l0 + t)*CONV_DIM;
            xs[t][c]  = conv[base + h*64 + c];
            Bsh[t][c] = conv[base + DSSM + c];
            Csh[t][c] = conv[base + DSSM + MS + c];
        }
        for (int i = tid; i < SCT; i += 256) {
            float r = proj[(size_t)(b*L_ + l0 + i)*PROJ_DIM + (PROJ_DIM-MH) + h] * 1.2f + dtb;
            dts[i] = (r > 20.f) ? r : log1pf(expf(r));   // softplus
        }
        __syncthreads();
        for (int t = 0; t < SCT; ++t) {
            float dt = dts[t];
            float dA = __expf(dt * Ah);
            float xv = xs[t][p];
            float coef = dt * xv;
            float acc = 0.f;
            #pragma unroll
            for (int ss = 0; ss < 16; ++ss) {
                st[ss] = st[ss]*dA + coef*Bsh[t][s0+ss];
                acc = fmaf(st[ss], Csh[t][s0+ss], acc);
            }
            acc += __shfl_xor_sync(0xffffffffu, acc, 1);
            acc += __shfl_xor_sync(0xffffffffu, acc, 2);
            if (sg == 0)
                y[(size_t)(b*L_ + l0 + t)*DSSM + h*64 + p] = acc + xv*Dh;
        }
    }
}

// ---------------- gating + RMS -> fp16 ----------------
__global__ __launch_bounds__(256) void gate_rms_kernel(
    const float* __restrict__ y, const float* __restrict__ proj,
    const float* __restrict__ w, __half* __restrict__ out)
{
    int m = blockIdx.x;
    const float* yr = y + (size_t)m*DSSM;
    const float* zr = proj + (size_t)m*PROJ_DIM;
    float v[8]; float ss = 0.f;
    #pragma unroll
    for (int k = 0; k < 8; ++k) {
        int c = threadIdx.x + k*256;
        float z = zr[c];
        float gv = yr[c] * siluf(z);
        v[k] = gv; ss += gv*gv;
    }
    ss = blockReduceSum256(ss);
    __shared__ float s_inv;
    if (threadIdx.x == 0) s_inv = rsqrtf(ss * (1.f/DSSM) + EPS_);
    __syncthreads();
    float inv = s_inv;
    __half* o = out + (size_t)m*DSSM;
    #pragma unroll
    for (int k = 0; k < 8; ++k) { int c = threadIdx.x + k*256; o[c] = __float2half_rn(v[k]*inv*w[c]); }
}

// ---------------- combine: h = as + residual ; hn16 = f16(rms(h)*w) ----------------
__global__ __launch_bounds__(256) void combine_kernel(
    const float* __restrict__ as_, const float* __restrict__ resid,
    const float* __restrict__ w, float* __restrict__ h, __half* __restrict__ hn)
{
    int m = blockIdx.x;
    const float* ar = as_  + (size_t)m*HID;
    const float* rr = resid + (size_t)m*HID;
    float v[8]; float ss = 0.f;
    #pragma unroll
    for (int k = 0; k < 8; ++k) {
        int c = threadIdx.x + k*256;
        float hv = ar[c] + rr[c];
        v[k] = hv; ss += hv*hv;
    }
    ss = blockReduceSum256(ss);
    __shared__ float s_inv;
    if (threadIdx.x == 0) s_inv = rsqrtf(ss * (1.f/HID) + EPS_);
    __syncthreads();
    float inv = s_inv;
    float* ho = h + (size_t)m*HID;
    __half* no = hn + (size_t)m*HID;
    #pragma unroll
    for (int k = 0; k < 8; ++k) {
        int c = threadIdx.x + k*256;
        ho[c] = v[k];
        no[c] = __float2half_rn(v[k]*inv*w[c]);
    }
}

// ---------------- SwiGLU activation on fp16 gu -> fp16 ----------------
__global__ void act_kernel(const __half* __restrict__ gu, __half* __restrict__ act) {
    int idx = blockIdx.x*256 + threadIdx.x;
    if (idx >= MROWS*INTER/2) return;
    int m = idx / (INTER/2);
    int i = (idx % (INTER/2)) * 2;
    const __half* row = gu + (size_t)m*(2*INTER);
    __half2 g2 = *(const __half2*)(row + i);
    __half2 u2 = *(const __half2*)(row + INTER + i);
    float g0 = __half2float(g2.x) * GATE_MULT;
    float g1 = __half2float(g2.y) * GATE_MULT;
    float a0 = siluf(g0) * __half2float(u2.x);
    float a1 = siluf(g1) * __half2float(u2.y);
    *(uint32_t*)(act + (size_t)m*INTER + i) = packh2(a0, a1);
}

// ---------------- host launcher (three-stream fork/join, graph-capture safe) -----
extern "C" void kernel_launch(void* const* d_in, const int* in_sizes, int n_in,
                              void* d_out, int out_size)
{
    const float* hidden      = (const float*)d_in[0];
    const int*   positions   = (const int*)  d_in[1];
    const float* w_in_ln     = (const float*)d_in[2];
    const float* qkv_w       = (const float*)d_in[3];
    const float* o_w         = (const float*)d_in[4];
    const float* in_proj_w   = (const float*)d_in[5];
    const float* conv_w      = (const float*)d_in[6];
    const float* conv_b      = (const float*)d_in[7];
    const float* A_log       = (const float*)d_in[8];
    const float* dt_bias     = (const float*)d_in[9];
    const float* Dp          = (const float*)d_in[10];
    const float* ssm_norm_w  = (const float*)d_in[11];
    const float* out_proj_w  = (const float*)d_in[12];
    const float* w_pre_ff_ln = (const float*)d_in[13];
    const float* gate_up_w   = (const float*)d_in[14];
    const float* down_w      = (const float*)d_in[15];
    float* out = (float*)d_out;

    float *proj, *conv, *y, *as_, *h;
    __half *qkv16, *gu16, *hs16, *ctx16, *gt16, *hn16, *act16, *w16, *q16, *k16, *v16t;
    cudaGetSymbolAddress((void**)&proj, g_proj);
    cudaGetSymbolAddress((void**)&conv, g_conv);
    cudaGetSymbolAddress((void**)&y,    g_y);
    cudaGetSymbolAddress((void**)&as_,  g_as);
    cudaGetSymbolAddress((void**)&h,    g_h);
    cudaGetSymbolAddress((void**)&qkv16,g_qkv16);
    cudaGetSymbolAddress((void**)&gu16, g_gu16);
    cudaGetSymbolAddress((void**)&hs16, g_hs16);
    cudaGetSymbolAddress((void**)&ctx16,g_ctx16);
    cudaGetSymbolAddress((void**)&gt16, g_gt16);
    cudaGetSymbolAddress((void**)&hn16, g_hn16);
    cudaGetSymbolAddress((void**)&act16,g_act16);
    cudaGetSymbolAddress((void**)&w16,  g_w16);
    cudaGetSymbolAddress((void**)&q16,  g_q16);
    cudaGetSymbolAddress((void**)&k16,  g_k16);
    cudaGetSymbolAddress((void**)&v16t, g_v16t);

    cudaFuncSetAttribute(gemm_f16,  cudaFuncAttributeMaxDynamicSharedMemorySize, GSMEM_BYTES);
    cudaFuncSetAttribute(gemm_f16h, cudaFuncAttributeMaxDynamicSharedMemorySize, GSMEM_BYTES);

    // side streams + events, created once (same captured work on every call)
    static cudaStream_t s2 = nullptr, s3 = nullptr;
    static cudaEvent_t ev_fork, ev_cvt, ev_rms, ev_o;
    if (!s2) {
        cudaStreamCreateWithFlags(&s2, cudaStreamNonBlocking);
        cudaStreamCreateWithFlags(&s3, cudaStreamNonBlocking);
        cudaEventCreateWithFlags(&ev_fork, cudaEventDisableTiming);
        cudaEventCreateWithFlags(&ev_cvt,  cudaEventDisableTiming);
        cudaEventCreateWithFlags(&ev_rms,  cudaEventDisableTiming);
        cudaEventCreateWithFlags(&ev_o,    cudaEventDisableTiming);
    }

    const int MT = MROWS/TBM;   // 16

    #define CVT_S(src, dstoff, n, strm) \
        cvt_f16_kernel<<<((n)/4 + 255)/256, 256, 0, strm>>>(src, w16 + (size_t)(dstoff), (n)/4)

    // ---- fork to s3: non-critical weight cvts ----
    cudaEventRecord(ev_fork, 0);
    cudaStreamWaitEvent(s3, ev_fork, 0);
    CVT_S(o_w,        W16_O,       HID*HID,     s3);
    CVT_S(out_proj_w, W16_OUTPROJ, HID*DSSM,    s3);
    CVT_S(gate_up_w,  W16_GATEUP,  2*INTER*HID, s3);
    CVT_S(down_w,     W16_DOWN,    HID*INTER,   s3);
    cudaEventRecord(ev_cvt, s3);

    // ---- main: critical cvts + shared rms ----
    CVT_S(qkv_w,     W16_QKV,    QKV_DIM*HID,  0);
    CVT_S(in_proj_w, W16_INPROJ, PROJ_DIM*HID, 0);
    rms_kernel<<<MROWS, 256>>>(hidden, w_in_ln, hs16);
    cudaEventRecord(ev_rms, 0);

    // ---- s2: attention branch (qkv GEMM -> rope -> vtrans -> attn -> o GEMM) ----
    cudaStreamWaitEvent(s2, ev_rms, 0);
    gemm_f16h<<<dim3(QKV_DIM/TBN, MT), 256, GSMEM_BYTES, s2>>>(QKV_DIM, HID, ATTN_IN,
                                            hs16, w16 + W16_QKV, qkv16);
    rope_kernel<<<(MROWS*(NH+NKV)*32 + 255)/256, 256, 0, s2>>>(qkv16, positions, q16, k16);
    vtrans_kernel<<<dim3(L_/64, NKV, B_), 256, 0, s2>>>(qkv16, v16t);
    attn_kernel<<<dim3(L_/64, NH, B_), 128, 0, s2>>>(q16, k16, v16t, ctx16);
    cudaStreamWaitEvent(s2, ev_cvt, 0);
    gemm_f16<<<dim3(HID/TBN, MT), 256, GSMEM_BYTES, s2>>>(HID, HID, ATTN_OUT,
                                            ctx16, w16 + W16_O, 0.f, nullptr, as_);
    cudaEventRecord(ev_o, s2);

    // ---- main: mamba branch (proj GEMM -> conv -> scan -> gate_rms) ----
    gemm_f16<<<dim3((PROJ_DIM+TBN-1)/TBN, MT), 256, GSMEM_BYTES>>>(PROJ_DIM, HID, SSM_IN,
                                            hs16, w16 + W16_INPROJ, 0.f, nullptr, proj);
    conv_kernel<<<(MROWS*CONV_DIM + 255)/256, 256>>>(proj, conv_w, conv_b, conv);
    scan_kernel<<<B_*MH, 256>>>(conv, proj, A_log, dt_bias, Dp, y);
    gate_rms_kernel<<<MROWS, 256>>>(y, proj, ssm_norm_w, gt16);

    // ---- join: out_proj accumulates into as_ (after o GEMM; ev_o orders ev_cvt too)
    cudaStreamWaitEvent(0, ev_o, 0);
    gemm_f16<<<dim3(HID/TBN, MT), 256, GSMEM_BYTES>>>(HID, DSSM, SSM_OUT,
                                            gt16, w16 + W16_OUTPROJ, 1.f, as_, as_);

    combine_kernel<<<MROWS, 256>>>(as_, hidden, w_pre_ff_ln, h, hn16);

    gemm_f16h<<<dim3(2*INTER/TBN, MT), 256, GSMEM_BYTES>>>(2*INTER, HID, 1.f,
                                            hn16, w16 + W16_GATEUP, gu16);
    act_kernel<<<(MROWS*INTER/2 + 255)/256, 256>>>(gu16, act16);
    gemm_f16<<<dim3(HID/TBN, MT), 256, GSMEM_BYTES>>>(HID, INTER, DOWN_MULT,
                                            act16, w16 + W16_DOWN, 1.f, h, out);
    #undef CVT_S
    (void)in_sizes; (void)n_in; (void)out_size;
}

// round 17
// speedup vs baseline: 1.3120x; 1.0024x over previous
#include <cuda_runtime.h>
#include <cuda_fp16.h>
#include <math.h>
#include <stdint.h>

#define B_ 2
#define L_ 1024
#define HID 2048
#define NH 32
#define HD 64
#define NKV 8
#define INTER 8192
#define DSSM 2048
#define MH 32
#define MP 64
#define MS 64
#define MK 4
#define CONV_DIM (DSSM + 2*MS)          // 2176
#define PROJ_DIM (2*DSSM + 2*MS + MH)   // 4256
#define QKV_DIM (NH*HD + 2*NKV*HD)      // 3072
#define MROWS (B_*L_)                   // 2048

#define ATTN_IN 1.2f
#define ATTN_OUT 0.8f
#define KEY_MULT 0.7f
#define SSM_IN 1.1f
#define SSM_OUT 0.9f
#define GATE_MULT 0.9f
#define DOWN_MULT 0.8f
#define EPS_ 1e-5f

// ---------------- scratch (device globals; no allocation allowed) ----------------
__device__ float  g_proj[MROWS*PROJ_DIM];
__device__ float  g_conv[MROWS*CONV_DIM];
__device__ float  g_y   [MROWS*DSSM];
__device__ float  g_as1 [MROWS*HID];
__device__ float  g_as2 [MROWS*HID];
__device__ float  g_h   [MROWS*HID];

__device__ __half g_qkv16[MROWS*QKV_DIM];
__device__ __half g_gu16 [(size_t)MROWS*2*INTER];
__device__ __half g_hs16 [MROWS*HID];
__device__ __half g_ctx16[MROWS*HID];
__device__ __half g_gt16 [MROWS*DSSM];
__device__ __half g_hn16 [MROWS*HID];
__device__ __half g_act16[(size_t)MROWS*INTER];
__device__ __half g_q16  [MROWS*NH*HD];
__device__ __half g_k16  [B_*NKV*L_*HD];
__device__ __half g_v16t [B_*NKV*HD*L_];

// fp16 weights, one big buffer
#define W16_QKV     0
#define W16_INPROJ  (W16_QKV    + QKV_DIM*HID)
#define W16_O       (W16_INPROJ + PROJ_DIM*HID)
#define W16_OUTPROJ (W16_O      + HID*HID)
#define W16_GATEUP  (W16_OUTPROJ+ HID*DSSM)
#define W16_DOWN    (W16_GATEUP + 2*INTER*HID)
#define W16_TOTAL   (W16_DOWN   + HID*INTER)
__device__ __half g_w16[W16_TOTAL];

// ---------------- helpers ----------------
__device__ __forceinline__ float blockReduceSum256(float v) {
    __shared__ float sh[8];
    int lane = threadIdx.x & 31, w = threadIdx.x >> 5;
    #pragma unroll
    for (int o = 16; o; o >>= 1) v += __shfl_xor_sync(0xffffffffu, v, o);
    if (lane == 0) sh[w] = v;
    __syncthreads();
    v = (threadIdx.x < 8) ? sh[threadIdx.x] : 0.f;
    if (w == 0) {
        #pragma unroll
        for (int o = 4; o; o >>= 1) v += __shfl_xor_sync(0xffu, v, o);
    }
    return v;
}

__device__ __forceinline__ float siluf(float x) { return x / (1.f + __expf(-x)); }

__device__ __forceinline__ void mma_f16(float* c, const uint32_t* a, const uint32_t* b) {
    asm volatile(
        "mma.sync.aligned.m16n8k16.row.col.f32.f16.f16.f32 "
        "{%0,%1,%2,%3}, {%4,%5,%6,%7}, {%8,%9}, {%0,%1,%2,%3};"
        : "+f"(c[0]), "+f"(c[1]), "+f"(c[2]), "+f"(c[3])
        : "r"(a[0]), "r"(a[1]), "r"(a[2]), "r"(a[3]), "r"(b[0]), "r"(b[1]));
}

__device__ __forceinline__ uint32_t smem_u32(const void* p) {
    uint32_t a;
    asm("{ .reg .u64 t; cvta.to.shared.u64 t, %1; cvt.u32.u64 %0, t; }" : "=r"(a) : "l"(p));
    return a;
}
__device__ __forceinline__ void cp_async16(uint32_t dst, const void* src, int srcBytes) {
    asm volatile("cp.async.cg.shared.global [%0], [%1], 16, %2;"
                 :: "r"(dst), "l"(src), "r"(srcBytes));
}
#define CP_COMMIT() asm volatile("cp.async.commit_group;" ::: "memory")
#define CP_WAIT1()  asm volatile("cp.async.wait_group 1;"  ::: "memory")

__device__ __forceinline__ uint32_t packh2(float a, float b) {
    __half2 h = __floats2half2_rn(a, b);
    return *(uint32_t*)&h;
}

// ---------------- fp32 -> fp16 weight convert (coalesced, 1 float4/thread) -------
__global__ void cvt_f16_kernel(const float* __restrict__ in, __half* __restrict__ out, int n4) {
    int i = blockIdx.x*256 + threadIdx.x;
    if (i >= n4) return;
    float4 v = *(const float4*)(in + (size_t)i*4);
    *(uint2*)(out + (size_t)i*4) = make_uint2(packh2(v.x, v.y), packh2(v.z, v.w));
}

// ---------------- FP16 tensor-core GEMM (fp32 out, alpha/beta) ----------------
#define TBM 128
#define TBN 128
#define TBK 64
#define TSTP 36
#define STGP (128*TSTP)
#define GSMEM_BYTES (4*STGP*4)           // 73728 B

__global__ __launch_bounds__(256, 2) void gemm_f16(
    int Ni, int Ki, float alpha,
    const __half* __restrict__ A, const __half* __restrict__ Bw,
    float beta, const float* __restrict__ Cin, float* __restrict__ C)
{
    extern __shared__ uint32_t smp[];
    uint32_t* As[2] = { smp,          smp + 2*STGP };
    uint32_t* Bs[2] = { smp + STGP,   smp + 3*STGP };

    const int tid = threadIdx.x;
    const int bm = blockIdx.y * TBM, bn = blockIdx.x * TBN;
    const int warp = tid >> 5, lane = tid & 31;
    const int g = lane >> 2, t = lane & 3;
    const int wm = (warp >> 2) * 64;
    const int wn = (warp & 3) * 32;

    const int lrow = tid >> 3;
    const int lch  = tid & 7;

    const int nk = Ki / TBK;

    {
        #pragma unroll
        for (int q = 0; q < 4; ++q) {
            int row = lrow + q*32;
            cp_async16(smem_u32(As[0] + row*TSTP + lch*4),
                       A + (size_t)(bm + row)*Ki + lch*8, 16);
            int brow = bn + row;
            const __half* srcB = Bw + (size_t)(brow < Ni ? brow : 0)*Ki + lch*8;
            cp_async16(smem_u32(Bs[0] + row*TSTP + lch*4), srcB, brow < Ni ? 16 : 0);
        }
        CP_COMMIT();
    }

    float acc[4][4][4];
    #pragma unroll
    for (int i = 0; i < 4; ++i)
        #pragma unroll
        for (int j = 0; j < 4; ++j)
            #pragma unroll
            for (int r = 0; r < 4; ++r) acc[i][j][r] = 0.f;

    for (int j = 0; j < nk; ++j) {
        const int b = j & 1;
        if (j + 1 < nk) {
            const int k0 = (j + 1) * TBK;
            const int nb = b ^ 1;
            #pragma unroll
            for (int q = 0; q < 4; ++q) {
                int row = lrow + q*32;
                cp_async16(smem_u32(As[nb] + row*TSTP + lch*4),
                           A + (size_t)(bm + row)*Ki + k0 + lch*8, 16);
                int brow = bn + row;
                const __half* srcB = Bw + (size_t)(brow < Ni ? brow : 0)*Ki + k0 + lch*8;
                cp_async16(smem_u32(Bs[nb] + row*TSTP + lch*4), srcB, brow < Ni ? 16 : 0);
            }
        }
        CP_COMMIT();
        CP_WAIT1();
        __syncthreads();

        const uint32_t* as = As[b];
        const uint32_t* bs = Bs[b];
        #pragma unroll
        for (int ks = 0; ks < TBK/16; ++ks) {
            uint32_t af[4][4];
            #pragma unroll
            for (int i = 0; i < 4; ++i) {
                const uint32_t* r0 = as + (wm + i*16 + g)*TSTP + ks*8 + t;
                const uint32_t* r1 = r0 + 8*TSTP;
                af[i][0] = r0[0];
                af[i][1] = r1[0];
                af[i][2] = r0[4];
                af[i][3] = r1[4];
            }
            uint32_t bf[4][2];
            #pragma unroll
            for (int jj = 0; jj < 4; ++jj) {
                const uint32_t* base = bs + (wn + jj*8 + g)*TSTP + ks*8 + t;
                bf[jj][0] = base[0];
                bf[jj][1] = base[4];
            }
            #pragma unroll
            for (int i = 0; i < 4; ++i)
                #pragma unroll
                for (int jj = 0; jj < 4; ++jj)
                    mma_f16(acc[i][jj], af[i], bf[jj]);
        }
        __syncthreads();
    }

    #pragma unroll
    for (int i = 0; i < 4; ++i) {
        int row0 = bm + wm + i*16 + g;
        #pragma unroll
        for (int j = 0; j < 4; ++j) {
            int col = bn + wn + j*8 + 2*t;
            if (col >= Ni) continue;
            size_t o0 = (size_t)row0 * Ni + col;
            size_t o1 = (size_t)(row0 + 8) * Ni + col;
            float2 v0 = make_float2(alpha*acc[i][j][0], alpha*acc[i][j][1]);
            float2 v1 = make_float2(alpha*acc[i][j][2], alpha*acc[i][j][3]);
            if (beta != 0.f) {
                float2 e0 = *(const float2*)(Cin + o0);
                float2 e1 = *(const float2*)(Cin + o1);
                v0.x += beta*e0.x; v0.y += beta*e0.y;
                v1.x += beta*e1.x; v1.y += beta*e1.y;
            }
            *(float2*)(C + o0) = v0;
            *(float2*)(C + o1) = v1;
        }
    }
}

// ---------------- FP16 GEMM, fp16 output (alpha only) ----------------
__global__ __launch_bounds__(256, 2) void gemm_f16h(
    int Ni, int Ki, float alpha,
    const __half* __restrict__ A, const __half* __restrict__ Bw,
    __half* __restrict__ C)
{
    extern __shared__ uint32_t smp[];
    uint32_t* As[2] = { smp,          smp + 2*STGP };
    uint32_t* Bs[2] = { smp + STGP,   smp + 3*STGP };

    const int tid = threadIdx.x;
    const int bm = blockIdx.y * TBM, bn = blockIdx.x * TBN;
    const int warp = tid >> 5, lane = tid & 31;
    const int g = lane >> 2, t = lane & 3;
    const int wm = (warp >> 2) * 64;
    const int wn = (warp & 3) * 32;

    const int lrow = tid >> 3;
    const int lch  = tid & 7;

    const int nk = Ki / TBK;

    {
        #pragma unroll
        for (int q = 0; q < 4; ++q) {
            int row = lrow + q*32;
            cp_async16(smem_u32(As[0] + row*TSTP + lch*4),
                       A + (size_t)(bm + row)*Ki + lch*8, 16);
            int brow = bn + row;
            const __half* srcB = Bw + (size_t)(brow < Ni ? brow : 0)*Ki + lch*8;
            cp_async16(smem_u32(Bs[0] + row*TSTP + lch*4), srcB, brow < Ni ? 16 : 0);
        }
        CP_COMMIT();
    }

    float acc[4][4][4];
    #pragma unroll
    for (int i = 0; i < 4; ++i)
        #pragma unroll
        for (int j = 0; j < 4; ++j)
            #pragma unroll
            for (int r = 0; r < 4; ++r) acc[i][j][r] = 0.f;

    for (int j = 0; j < nk; ++j) {
        const int b = j & 1;
        if (j + 1 < nk) {
            const int k0 = (j + 1) * TBK;
            const int nb = b ^ 1;
            #pragma unroll
            for (int q = 0; q < 4; ++q) {
                int row = lrow + q*32;
                cp_async16(smem_u32(As[nb] + row*TSTP + lch*4),
                           A + (size_t)(bm + row)*Ki + k0 + lch*8, 16);
                int brow = bn + row;
                const __half* srcB = Bw + (size_t)(brow < Ni ? brow : 0)*Ki + k0 + lch*8;
                cp_async16(smem_u32(Bs[nb] + row*TSTP + lch*4), srcB, brow < Ni ? 16 : 0);
            }
        }
        CP_COMMIT();
        CP_WAIT1();
        __syncthreads();

        const uint32_t* as = As[b];
        const uint32_t* bs = Bs[b];
        #pragma unroll
        for (int ks = 0; ks < TBK/16; ++ks) {
            uint32_t af[4][4];
            #pragma unroll
            for (int i = 0; i < 4; ++i) {
                const uint32_t* r0 = as + (wm + i*16 + g)*TSTP + ks*8 + t;
                const uint32_t* r1 = r0 + 8*TSTP;
                af[i][0] = r0[0];
                af[i][1] = r1[0];
                af[i][2] = r0[4];
                af[i][3] = r1[4];
            }
            uint32_t bf[4][2];
            #pragma unroll
            for (int jj = 0; jj < 4; ++jj) {
                const uint32_t* base = bs + (wn + jj*8 + g)*TSTP + ks*8 + t;
                bf[jj][0] = base[0];
                bf[jj][1] = base[4];
            }
            #pragma unroll
            for (int i = 0; i < 4; ++i)
                #pragma unroll
                for (int jj = 0; jj < 4; ++jj)
                    mma_f16(acc[i][jj], af[i], bf[jj]);
        }
        __syncthreads();
    }

    #pragma unroll
    for (int i = 0; i < 4; ++i) {
        int row0 = bm + wm + i*16 + g;
        #pragma unroll
        for (int j = 0; j < 4; ++j) {
            int col = bn + wn + j*8 + 2*t;
            if (col >= Ni) continue;
            *(uint32_t*)(C + (size_t)row0 * Ni + col) =
                packh2(alpha*acc[i][j][0], alpha*acc[i][j][1]);
            *(uint32_t*)(C + (size_t)(row0 + 8) * Ni + col) =
                packh2(alpha*acc[i][j][2], alpha*acc[i][j][3]);
        }
    }
}

// ---------------- RMS norm: hs16 = f16(rms(x)*w) ----------------
__global__ __launch_bounds__(256) void rms_kernel(
    const float* __restrict__ x, const float* __restrict__ w, __half* __restrict__ out)
{
    int m = blockIdx.x;
    const float* xr = x + (size_t)m * HID;
    float v[8]; float ss = 0.f;
    #pragma unroll
    for (int k = 0; k < 8; ++k) { v[k] = xr[threadIdx.x + k*256]; ss += v[k]*v[k]; }
    ss = blockReduceSum256(ss);
    __shared__ float s_inv;
    if (threadIdx.x == 0) s_inv = rsqrtf(ss * (1.f/HID) + EPS_);
    __syncthreads();
    float inv = s_inv;
    __half* o = out + (size_t)m * HID;
    #pragma unroll
    for (int k = 0; k < 8; ++k) { int c = threadIdx.x + k*256; o[c] = __float2half_rn(v[k]*inv*w[c]); }
}

// ---------------- RoPE on fp16 qkv -> fp16 q (x1/8) and k (head-major) ----------
__global__ void rope_kernel(const __half* __restrict__ qkv, const int* __restrict__ positions,
                            __half* __restrict__ q16, __half* __restrict__ k16) {
    int idx = blockIdx.x*256 + threadIdx.x;
    const int total = MROWS*(NH+NKV)*32;
    if (idx >= total) return;
    int i = idx & 31; int rest = idx >> 5;
    int head = rest % (NH+NKV); int ml = rest / (NH+NKV);
    int l = ml % L_, b = ml / L_;
    float inv = powf(1e11f, -(float)i/32.0f);
    float ang = (float)positions[l] * inv;
    float c = cosf(ang), s = sinf(ang);
    if (head < NH) {
        const __half* p = qkv + (size_t)ml*QKV_DIM + head*HD;
        float x1 = __half2float(p[i]), x2 = __half2float(p[i+32]);
        __half* o = q16 + (size_t)ml*(NH*HD) + head*HD;
        o[i]    = __float2half_rn((x1*c - x2*s) * 0.125f);
        o[i+32] = __float2half_rn((x2*c + x1*s) * 0.125f);
    } else {
        int g = head - NH;
        const __half* p = qkv + (size_t)ml*QKV_DIM + NH*HD + g*HD;
        float x1 = __half2float(p[i])*KEY_MULT, x2 = __half2float(p[i+32])*KEY_MULT;
        __half* o = k16 + ((size_t)(b*NKV + g)*L_ + l)*HD;
        o[i]    = __float2half_rn(x1*c - x2*s);
        o[i+32] = __float2half_rn(x2*c + x1*s);
    }
}

// ---------------- V transpose: fp16 qkv v-part -> v16t [b][g][d][L] --------------
__global__ __launch_bounds__(256) void vtrans_kernel(
    const __half* __restrict__ qkv, __half* __restrict__ v16t)
{
    __shared__ __half ts[64][65];
    const int lt = blockIdx.x, g = blockIdx.y, b = blockIdx.z;
    const int vcol = NH*HD + NKV*HD + g*HD;
    const int tid = threadIdx.x;
    #pragma unroll
    for (int q = 0; q < 16; ++q) {
        int idx = tid + q*256;
        int row = idx >> 6, col = idx & 63;
        ts[col][row] = qkv[(size_t)(b*L_ + lt*64 + row)*QKV_DIM + vcol + col];
    }
    __syncthreads();
    #pragma unroll
    for (int q = 0; q < 16; ++q) {
        int idx = tid + q*256;
        int d = idx >> 6, l = idx & 63;
        v16t[((size_t)(b*NKV + g)*HD + d)*L_ + lt*64 + l] = ts[d][l];
    }
}

// ---------------- tensor-core flash attention (causal, GQA, HD=64) --------------
__global__ __launch_bounds__(128) void attn_kernel(
    const __half* __restrict__ q16, const __half* __restrict__ k16,
    const __half* __restrict__ v16t, __half* __restrict__ ctx)
{
    __shared__ uint32_t Qs[64*36];
    __shared__ uint32_t Ks[64*36];
    __shared__ uint32_t Vs[64*36];
    const int tid = threadIdx.x;
    const int warp = tid >> 5, lane = tid & 31;
    const int g = lane >> 2, t = lane & 3;
    const int wm = warp*16;
    const int qb = blockIdx.x, h = blockIdx.y, b = blockIdx.z;
    const int kg = h >> 2;

    {
        const __half* qp = q16 + (size_t)(b*L_ + qb*64)*(NH*HD) + h*HD;
        #pragma unroll
        for (int q = 0; q < 4; ++q) {
            int idx = tid + q*128;
            int row = idx >> 3, ch = idx & 7;
            *(uint4*)(&Qs[row*36 + ch*4]) =
                *(const uint4*)(qp + (size_t)row*(NH*HD) + ch*8);
        }
    }
    __syncthreads();

    uint32_t aq[4][4];
    #pragma unroll
    for (int ks = 0; ks < 4; ++ks) {
        const uint32_t* r0 = Qs + (wm + g)*36 + ks*8 + t;
        const uint32_t* r1 = Qs + (wm + g + 8)*36 + ks*8 + t;
        aq[ks][0] = r0[0]; aq[ks][1] = r1[0]; aq[ks][2] = r0[4]; aq[ks][3] = r1[4];
    }

    float oacc[8][4];
    #pragma unroll
    for (int jj = 0; jj < 8; ++jj)
        #pragma unroll
        for (int r = 0; r < 4; ++r) oacc[jj][r] = 0.f;
    float m_a = -1e30f, m_b = -1e30f, l_a = 0.f, l_b = 0.f;

    const __half* kp = k16 + (size_t)(b*NKV + kg)*L_*HD;
    const __half* vp = v16t + (size_t)(b*NKV + kg)*HD*L_;

    for (int j = 0; j <= qb; ++j) {
        __syncthreads();
        #pragma unroll
        for (int q = 0; q < 4; ++q) {
            int idx = tid + q*128;
            int row = idx >> 3, ch = idx & 7;
            *(uint4*)(&Ks[row*36 + ch*4]) =
                *(const uint4*)(kp + (size_t)(j*64 + row)*HD + ch*8);
            *(uint4*)(&Vs[row*36 + ch*4]) =
                *(const uint4*)(vp + (size_t)row*L_ + j*64 + ch*8);
        }
        __syncthreads();

        float sacc[8][4];
        #pragma unroll
        for (int jj = 0; jj < 8; ++jj)
            #pragma unroll
            for (int r = 0; r < 4; ++r) sacc[jj][r] = 0.f;
        #pragma unroll
        for (int ks = 0; ks < 4; ++ks) {
            #pragma unroll
            for (int jj = 0; jj < 8; ++jj) {
                uint32_t bk[2];
                const uint32_t* base = Ks + (jj*8 + g)*36 + ks*8 + t;
                bk[0] = base[0]; bk[1] = base[4];
                mma_f16(sacc[jj], aq[ks], bk);
            }
        }

        if (j == qb) {
            const int ra = wm + g, rb = ra + 8;
            #pragma unroll
            for (int jj = 0; jj < 8; ++jj) {
                int c0 = jj*8 + 2*t, c1 = c0 + 1;
                if (c0 > ra) sacc[jj][0] = -1e30f;
                if (c1 > ra) sacc[jj][1] = -1e30f;
                if (c0 > rb) sacc[jj][2] = -1e30f;
                if (c1 > rb) sacc[jj][3] = -1e30f;
            }
        }

        float mx_a = -1e30f, mx_b = -1e30f;
        #pragma unroll
        for (int jj = 0; jj < 8; ++jj) {
            mx_a = fmaxf(mx_a, fmaxf(sacc[jj][0], sacc[jj][1]));
            mx_b = fmaxf(mx_b, fmaxf(sacc[jj][2], sacc[jj][3]));
        }
        mx_a = fmaxf(mx_a, __shfl_xor_sync(0xffffffffu, mx_a, 1));
        mx_a = fmaxf(mx_a, __shfl_xor_sync(0xffffffffu, mx_a, 2));
        mx_b = fmaxf(mx_b, __shfl_xor_sync(0xffffffffu, mx_b, 1));
        mx_b = fmaxf(mx_b, __shfl_xor_sync(0xffffffffu, mx_b, 2));
        float mna = fmaxf(m_a, mx_a), mnb = fmaxf(m_b, mx_b);
        float ca = __expf(m_a - mna), cb = __expf(m_b - mnb);
        m_a = mna; m_b = mnb;
        float sa = 0.f, sb = 0.f;
        #pragma unroll
        for (int jj = 0; jj < 8; ++jj) {
            sacc[jj][0] = __expf(sacc[jj][0] - mna);
            sacc[jj][1] = __expf(sacc[jj][1] - mna);
            sacc[jj][2] = __expf(sacc[jj][2] - mnb);
            sacc[jj][3] = __expf(sacc[jj][3] - mnb);
            sa += sacc[jj][0] + sacc[jj][1];
            sb += sacc[jj][2] + sacc[jj][3];
        }
        sa += __shfl_xor_sync(0xffffffffu, sa, 1);
        sa += __shfl_xor_sync(0xffffffffu, sa, 2);
        sb += __shfl_xor_sync(0xffffffffu, sb, 1);
        sb += __shfl_xor_sync(0xffffffffu, sb, 2);
        l_a = l_a*ca + sa; l_b = l_b*cb + sb;
        #pragma unroll
        for (int jj = 0; jj < 8; ++jj) {
            oacc[jj][0] *= ca; oacc[jj][1] *= ca;
            oacc[jj][2] *= cb; oacc[jj][3] *= cb;
        }

        uint32_t aP[4][4];
        #pragma unroll
        for (int s = 0; s < 4; ++s) {
            aP[s][0] = packh2(sacc[2*s][0],   sacc[2*s][1]);
            aP[s][1] = packh2(sacc[2*s][2],   sacc[2*s][3]);
            aP[s][2] = packh2(sacc[2*s+1][0], sacc[2*s+1][1]);
            aP[s][3] = packh2(sacc[2*s+1][2], sacc[2*s+1][3]);
        }

        #pragma unroll
        for (int s = 0; s < 4; ++s) {
            #pragma unroll
            for (int jj = 0; jj < 8; ++jj) {
                uint32_t bv[2];
                const uint32_t* base = Vs + (jj*8 + g)*36 + s*8 + t;
                bv[0] = base[0]; bv[1] = base[4];
                mma_f16(oacc[jj], aP[s], bv);
            }
        }
    }

    float ila = 1.f / l_a, ilb = 1.f / l_b;
    int ra = qb*64 + wm + g;
    __half* op = ctx + (size_t)(b*L_ + ra)*HID + h*HD + 2*t;
    #pragma unroll
    for (int jj = 0; jj < 8; ++jj) {
        *(uint32_t*)(op + jj*8) = packh2(oacc[jj][0]*ila, oacc[jj][1]*ila);
        *(uint32_t*)(op + 8*HID + jj*8) = packh2(oacc[jj][2]*ilb, oacc[jj][3]*ilb);
    }
}

// ---------------- depthwise causal conv (MK=4) + mup + bias + SiLU ----------------
__global__ void conv_kernel(const float* __restrict__ proj, const float* __restrict__ cw,
                            const float* __restrict__ cb, float* __restrict__ out)
{
    int idx = blockIdx.x*256 + threadIdx.x;
    if (idx >= MROWS*CONV_DIM) return;
    int c = idx % CONV_DIM;
    int ml = idx / CONV_DIM;
    int l = ml % L_, b = ml / L_;
    float mupf = (c < DSSM) ? 0.9f : ((c < DSSM+MS) ? 0.8f : 1.1f);
    float s = 0.f;
    #pragma unroll
    for (int k = 0; k < MK; ++k) {
        int ls = l + k - (MK-1);
        if (ls >= 0) s += proj[(size_t)(b*L_+ls)*PROJ_DIM + DSSM + c] * cw[c*MK + k];
    }
    s = mupf*s + cb[c];
    out[idx] = siluf(s);
}

// ---------------- Mamba2 selective scan ----------------
#define SCT 32
__global__ __launch_bounds__(256) void scan_kernel(
    const float* __restrict__ conv, const float* __restrict__ proj,
    const float* __restrict__ A_log, const float* __restrict__ dt_bias,
    const float* __restrict__ Dp, float* __restrict__ y)
{
    const int b = blockIdx.x / MH, h = blockIdx.x % MH;
    const int tid = threadIdx.x;
    const int p = tid >> 2, sg = tid & 3, s0 = sg*16;
    const float Ah = -__expf(A_log[h]);
    const float Dh = Dp[h];
    const float dtb = dt_bias[h];
    float st[16];
    #pragma unroll
    for (int i = 0; i < 16; ++i) st[i] = 0.f;

    __shared__ float xs[SCT][64], Bsh[SCT][64], Csh[SCT][64], dts[SCT];

    for (int l0 = 0; l0 < L_; l0 += SCT) {
        __syncthreads();
        for (int i = tid; i < SCT*64; i += 256) {
            int t = i >> 6, c = i & 63;
            size_t base = (size_t)(b*L_ + l0 + t)*CONV_DIM;
            xs[t][c]  = conv[base + h*64 + c];
            Bsh[t][c] = conv[base + DSSM + c];
            Csh[t][c] = conv[base + DSSM + MS + c];
        }
        for (int i = tid; i < SCT; i += 256) {
            float r = proj[(size_t)(b*L_ + l0 + i)*PROJ_DIM + (PROJ_DIM-MH) + h] * 1.2f + dtb;
            dts[i] = (r > 20.f) ? r : log1pf(expf(r));   // softplus
        }
        __syncthreads();
        for (int t = 0; t < SCT; ++t) {
            float dt = dts[t];
            float dA = __expf(dt * Ah);
            float xv = xs[t][p];
            float coef = dt * xv;
            float acc = 0.f;
            #pragma unroll
            for (int ss = 0; ss < 16; ++ss) {
                st[ss] = st[ss]*dA + coef*Bsh[t][s0+ss];
                acc = fmaf(st[ss], Csh[t][s0+ss], acc);
            }
            acc += __shfl_xor_sync(0xffffffffu, acc, 1);
            acc += __shfl_xor_sync(0xffffffffu, acc, 2);
            if (sg == 0)
                y[(size_t)(b*L_ + l0 + t)*DSSM + h*64 + p] = acc + xv*Dh;
        }
    }
}

// ---------------- gating + RMS -> fp16 ----------------
__global__ __launch_bounds__(256) void gate_rms_kernel(
    const float* __restrict__ y, const float* __restrict__ proj,
    const float* __restrict__ w, __half* __restrict__ out)
{
    int m = blockIdx.x;
    const float* yr = y + (size_t)m*DSSM;
    const float* zr = proj + (size_t)m*PROJ_DIM;
    float v[8]; float ss = 0.f;
    #pragma unroll
    for (int k = 0; k < 8; ++k) {
        int c = threadIdx.x + k*256;
        float z = zr[c];
        float gv = yr[c] * siluf(z);
        v[k] = gv; ss += gv*gv;
    }
    ss = blockReduceSum256(ss);
    __shared__ float s_inv;
    if (threadIdx.x == 0) s_inv = rsqrtf(ss * (1.f/DSSM) + EPS_);
    __syncthreads();
    float inv = s_inv;
    __half* o = out + (size_t)m*DSSM;
    #pragma unroll
    for (int k = 0; k < 8; ++k) { int c = threadIdx.x + k*256; o[c] = __float2half_rn(v[k]*inv*w[c]); }
}

// ---------------- combine: h = as1 + as2 + residual ; hn16 = f16(rms(h)*w) -------
__global__ __launch_bounds__(256) void combine_kernel(
    const float* __restrict__ as1, const float* __restrict__ as2,
    const float* __restrict__ resid,
    const float* __restrict__ w, float* __restrict__ h, __half* __restrict__ hn)
{
    int m = blockIdx.x;
    const float* a1 = as1  + (size_t)m*HID;
    const float* a2 = as2  + (size_t)m*HID;
    const float* rr = resid + (size_t)m*HID;
    float v[8]; float ss = 0.f;
    #pragma unroll
    for (int k = 0; k < 8; ++k) {
        int c = threadIdx.x + k*256;
        float hv = a1[c] + a2[c] + rr[c];
        v[k] = hv; ss += hv*hv;
    }
    ss = blockReduceSum256(ss);
    __shared__ float s_inv;
    if (threadIdx.x == 0) s_inv = rsqrtf(ss * (1.f/HID) + EPS_);
    __syncthreads();
    float inv = s_inv;
    float* ho = h + (size_t)m*HID;
    __half* no = hn + (size_t)m*HID;
    #pragma unroll
    for (int k = 0; k < 8; ++k) {
        int c = threadIdx.x + k*256;
        ho[c] = v[k];
        no[c] = __float2half_rn(v[k]*inv*w[c]);
    }
}

// ---------------- SwiGLU activation on fp16 gu -> fp16 ----------------
__global__ void act_kernel(const __half* __restrict__ gu, __half* __restrict__ act) {
    int idx = blockIdx.x*256 + threadIdx.x;
    if (idx >= MROWS*INTER/2) return;
    int m = idx / (INTER/2);
    int i = (idx % (INTER/2)) * 2;
    const __half* row = gu + (size_t)m*(2*INTER);
    __half2 g2 = *(const __half2*)(row + i);
    __half2 u2 = *(const __half2*)(row + INTER + i);
    float g0 = __half2float(g2.x) * GATE_MULT;
    float g1 = __half2float(g2.y) * GATE_MULT;
    float a0 = siluf(g0) * __half2float(u2.x);
    float a1 = siluf(g1) * __half2float(u2.y);
    *(uint32_t*)(act + (size_t)m*INTER + i) = packh2(a0, a1);
}

// ---------------- host launcher (three-stream fork/join, graph-capture safe) -----
extern "C" void kernel_launch(void* const* d_in, const int* in_sizes, int n_in,
                              void* d_out, int out_size)
{
    const float* hidden      = (const float*)d_in[0];
    const int*   positions   = (const int*)  d_in[1];
    const float* w_in_ln     = (const float*)d_in[2];
    const float* qkv_w       = (const float*)d_in[3];
    const float* o_w         = (const float*)d_in[4];
    const float* in_proj_w   = (const float*)d_in[5];
    const float* conv_w      = (const float*)d_in[6];
    const float* conv_b      = (const float*)d_in[7];
    const float* A_log       = (const float*)d_in[8];
    const float* dt_bias     = (const float*)d_in[9];
    const float* Dp          = (const float*)d_in[10];
    const float* ssm_norm_w  = (const float*)d_in[11];
    const float* out_proj_w  = (const float*)d_in[12];
    const float* w_pre_ff_ln = (const float*)d_in[13];
    const float* gate_up_w   = (const float*)d_in[14];
    const float* down_w      = (const float*)d_in[15];
    float* out = (float*)d_out;

    float *proj, *conv, *y, *as1, *as2, *h;
    __half *qkv16, *gu16, *hs16, *ctx16, *gt16, *hn16, *act16, *w16, *q16, *k16, *v16t;
    cudaGetSymbolAddress((void**)&proj, g_proj);
    cudaGetSymbolAddress((void**)&conv, g_conv);
    cudaGetSymbolAddress((void**)&y,    g_y);
    cudaGetSymbolAddress((void**)&as1,  g_as1);
    cudaGetSymbolAddress((void**)&as2,  g_as2);
    cudaGetSymbolAddress((void**)&h,    g_h);
    cudaGetSymbolAddress((void**)&qkv16,g_qkv16);
    cudaGetSymbolAddress((void**)&gu16, g_gu16);
    cudaGetSymbolAddress((void**)&hs16, g_hs16);
    cudaGetSymbolAddress((void**)&ctx16,g_ctx16);
    cudaGetSymbolAddress((void**)&gt16, g_gt16);
    cudaGetSymbolAddress((void**)&hn16, g_hn16);
    cudaGetSymbolAddress((void**)&act16,g_act16);
    cudaGetSymbolAddress((void**)&w16,  g_w16);
    cudaGetSymbolAddress((void**)&q16,  g_q16);
    cudaGetSymbolAddress((void**)&k16,  g_k16);
    cudaGetSymbolAddress((void**)&v16t, g_v16t);

    cudaFuncSetAttribute(gemm_f16,  cudaFuncAttributeMaxDynamicSharedMemorySize, GSMEM_BYTES);
    cudaFuncSetAttribute(gemm_f16h, cudaFuncAttributeMaxDynamicSharedMemorySize, GSMEM_BYTES);

    // side streams + events, created once (same captured work on every call)
    static cudaStream_t s2 = nullptr, s3 = nullptr;
    static cudaEvent_t ev_fork, ev_cvt, ev_rms, ev_o;
    if (!s2) {
        cudaStreamCreateWithFlags(&s2, cudaStreamNonBlocking);
        cudaStreamCreateWithFlags(&s3, cudaStreamNonBlocking);
        cudaEventCreateWithFlags(&ev_fork, cudaEventDisableTiming);
        cudaEventCreateWithFlags(&ev_cvt,  cudaEventDisableTiming);
        cudaEventCreateWithFlags(&ev_rms,  cudaEventDisableTiming);
        cudaEventCreateWithFlags(&ev_o,    cudaEventDisableTiming);
    }

    const int MT = MROWS/TBM;   // 16

    #define CVT_S(src, dstoff, n, strm) \
        cvt_f16_kernel<<<((n)/4 + 255)/256, 256, 0, strm>>>(src, w16 + (size_t)(dstoff), (n)/4)

    // ---- fork to s3: non-critical weight cvts ----
    cudaEventRecord(ev_fork, 0);
    cudaStreamWaitEvent(s3, ev_fork, 0);
    CVT_S(o_w,        W16_O,       HID*HID,     s3);
    CVT_S(out_proj_w, W16_OUTPROJ, HID*DSSM,    s3);
    CVT_S(gate_up_w,  W16_GATEUP,  2*INTER*HID, s3);
    CVT_S(down_w,     W16_DOWN,    HID*INTER,   s3);
    cudaEventRecord(ev_cvt, s3);

    // ---- main: critical cvts + shared rms ----
    CVT_S(qkv_w,     W16_QKV,    QKV_DIM*HID,  0);
    CVT_S(in_proj_w, W16_INPROJ, PROJ_DIM*HID, 0);
    rms_kernel<<<MROWS, 256>>>(hidden, w_in_ln, hs16);
    cudaEventRecord(ev_rms, 0);

    // ---- s2: attention branch (qkv GEMM -> rope -> vtrans -> attn -> o GEMM) ----
    cudaStreamWaitEvent(s2, ev_rms, 0);
    gemm_f16h<<<dim3(QKV_DIM/TBN, MT), 256, GSMEM_BYTES, s2>>>(QKV_DIM, HID, ATTN_IN,
                                            hs16, w16 + W16_QKV, qkv16);
    rope_kernel<<<(MROWS*(NH+NKV)*32 + 255)/256, 256, 0, s2>>>(qkv16, positions, q16, k16);
    vtrans_kernel<<<dim3(L_/64, NKV, B_), 256, 0, s2>>>(qkv16, v16t);
    attn_kernel<<<dim3(L_/64, NH, B_), 128, 0, s2>>>(q16, k16, v16t, ctx16);
    cudaStreamWaitEvent(s2, ev_cvt, 0);
    gemm_f16<<<dim3(HID/TBN, MT), 256, GSMEM_BYTES, s2>>>(HID, HID, ATTN_OUT,
                                            ctx16, w16 + W16_O, 0.f, nullptr, as1);
    cudaEventRecord(ev_o, s2);

    // ---- main: mamba branch (proj GEMM -> conv -> scan -> gate_rms -> out_proj) --
    gemm_f16<<<dim3((PROJ_DIM+TBN-1)/TBN, MT), 256, GSMEM_BYTES>>>(PROJ_DIM, HID, SSM_IN,
                                            hs16, w16 + W16_INPROJ, 0.f, nullptr, proj);
    conv_kernel<<<(MROWS*CONV_DIM + 255)/256, 256>>>(proj, conv_w, conv_b, conv);
    scan_kernel<<<B_*MH, 256>>>(conv, proj, A_log, dt_bias, Dp, y);
    gate_rms_kernel<<<MROWS, 256>>>(y, proj, ssm_norm_w, gt16);
    cudaStreamWaitEvent(0, ev_cvt, 0);       // out_proj weights ready
    gemm_f16<<<dim3(HID/TBN, MT), 256, GSMEM_BYTES>>>(HID, DSSM, SSM_OUT,
                                            gt16, w16 + W16_OUTPROJ, 0.f, nullptr, as2);

    // ---- join at combine (needs as1 from s2) ----
    cudaStreamWaitEvent(0, ev_o, 0);
    combine_kernel<<<MROWS, 256>>>(as1, as2, hidden, w_pre_ff_ln, h, hn16);

    gemm_f16h<<<dim3(2*INTER/TBN, MT), 256, GSMEM_BYTES>>>(2*INTER, HID, 1.f,
                                            hn16, w16 + W16_GATEUP, gu16);
    act_kernel<<<(MROWS*INTER/2 + 255)/256, 256>>>(gu16, act16);
    gemm_f16<<<dim3(HID/TBN, MT), 256, GSMEM_BYTES>>>(HID, INTER, DOWN_MULT,
                                            act16, w16 + W16_DOWN, 1.f, h, out);
    #undef CVT_S
    (void)in_sizes; (void)n_in; (void)out_size;
}